// round 11
// baseline (speedup 1.0000x reference)
#include <cuda_runtime.h>
#include <cuda_bf16.h>
#include <math.h>
#include <float.h>
#include <stdint.h>

// Problem constants
#define T_LEN   4096
#define C_DIM   2048
#define HQ      16
#define HKV     4
#define HD      128
#define WIN     1024
#define NKV     (HKV * HD)     // 512

// RoPE tables
__device__ float g_cos[T_LEN * 64];
__device__ float g_sin[T_LEN * 64];

// bf16 split operands
__device__ __nv_bfloat16 g_xh[T_LEN * C_DIM],  g_xl[T_LEN * C_DIM];
__device__ __nv_bfloat16 g_yh[T_LEN * C_DIM],  g_yl[T_LEN * C_DIM];
__device__ __nv_bfloat16 g_qsh[T_LEN * C_DIM], g_qsl[T_LEN * C_DIM];
__device__ __nv_bfloat16 g_ksh[T_LEN * NKV],   g_ksl[T_LEN * NKV];
__device__ __nv_bfloat16 g_vsh[T_LEN * NKV],   g_vsl[T_LEN * NKV];
__device__ __nv_bfloat16 g_wqt_h[C_DIM * C_DIM], g_wqt_l[C_DIM * C_DIM];
__device__ __nv_bfloat16 g_wkt_h[NKV * C_DIM],   g_wkt_l[NKV * C_DIM];
__device__ __nv_bfloat16 g_wvt_h[NKV * C_DIM],   g_wvt_l[NKV * C_DIM];
__device__ __nv_bfloat16 g_wot_h[C_DIM * C_DIM], g_wot_l[C_DIM * C_DIM];

#define SCQ_CONST 0.1275174541395871f  // 1/sqrt(128) * log2(e)

// ---------------------------------------------------------------------------
// helpers
// ---------------------------------------------------------------------------
__device__ __forceinline__ uint32_t smem_u32(const void* p) {
    return (uint32_t)__cvta_generic_to_shared(p);
}

__device__ __forceinline__ void split2(float a, float b, uint32_t& hi, uint32_t& lo) {
    __nv_bfloat16 ah = __float2bfloat16_rn(a);
    __nv_bfloat16 bh = __float2bfloat16_rn(b);
    __nv_bfloat162 h(ah, bh);
    hi = *(uint32_t*)&h;
    __nv_bfloat162 l(__float2bfloat16_rn(a - __bfloat162float(ah)),
                     __float2bfloat16_rn(b - __bfloat162float(bh)));
    lo = *(uint32_t*)&l;
}

#define LDMATRIX_X4(R0,R1,R2,R3,ADDR) \
    asm volatile("ldmatrix.sync.aligned.m8n8.x4.shared.b16 {%0,%1,%2,%3}, [%4];" \
        : "=r"(R0), "=r"(R1), "=r"(R2), "=r"(R3) : "r"(ADDR))

#define LDMATRIX_X4_T(R0,R1,R2,R3,ADDR) \
    asm volatile("ldmatrix.sync.aligned.m8n8.x4.trans.shared.b16 {%0,%1,%2,%3}, [%4];" \
        : "=r"(R0), "=r"(R1), "=r"(R2), "=r"(R3) : "r"(ADDR))

#define MMA_BF16(D, A0,A1,A2,A3, B0,B1) \
    asm volatile("mma.sync.aligned.m16n8k16.row.col.f32.bf16.bf16.f32 " \
        "{%0,%1,%2,%3}, {%4,%5,%6,%7}, {%8,%9}, {%0,%1,%2,%3};" \
        : "+f"((D)[0]), "+f"((D)[1]), "+f"((D)[2]), "+f"((D)[3]) \
        : "r"(A0), "r"(A1), "r"(A2), "r"(A3), "r"(B0), "r"(B1))

__device__ __forceinline__ void cp_async16(uint32_t dst, const void* src) {
    asm volatile("cp.async.cg.shared.global [%0], [%1], 16;" :: "r"(dst), "l"(src));
}
__device__ __forceinline__ void cp_commit() {
    asm volatile("cp.async.commit_group;" ::: "memory");
}
template <int NN> __device__ __forceinline__ void cp_wait() {
    asm volatile("cp.async.wait_group %0;" :: "n"(NN) : "memory");
}

// ---------------------------------------------------------------------------
// Prep: RoPE table
// ---------------------------------------------------------------------------
__global__ void rope_table_kernel()
{
    __shared__ float s_invf[64];
    if (threadIdx.x < 64) {
        double e = exp(-(double)threadIdx.x * (log(10000.0) / 64.0));
        s_invf[threadIdx.x] = (float)e;
    }
    __syncthreads();
    int idx = blockIdx.x * blockDim.x + threadIdx.x;
    if (idx >= T_LEN * 64) return;
    int t = idx >> 6;
    int j = idx & 63;
    float ang = (float)t * s_invf[j];
    float s, c;
    sincosf(ang, &s, &c);
    g_cos[idx] = c;
    g_sin[idx] = s;
}

// ---------------------------------------------------------------------------
// Prep: merged transposes + x split (z-dispatched)
// ---------------------------------------------------------------------------
__device__ __forceinline__ void transpose_split_body(
    const float* __restrict__ W, __nv_bfloat16* __restrict__ Th,
    __nv_bfloat16* __restrict__ Tl, int Kd, int Nd, int bx, int by)
{
    __shared__ float tile[32][33];
    const int x = threadIdx.x;
    const int y = threadIdx.y;
#pragma unroll
    for (int j = 0; j < 32; j += 8)
        tile[y + j][x] = W[(size_t)(by * 32 + y + j) * Nd + bx * 32 + x];
    __syncthreads();
#pragma unroll
    for (int j = 0; j < 32; j += 8) {
        float v = tile[x][y + j];
        __nv_bfloat16 h = __float2bfloat16_rn(v);
        size_t o = (size_t)(bx * 32 + y + j) * Kd + by * 32 + x;
        Th[o] = h;
        Tl[o] = __float2bfloat16_rn(v - __bfloat162float(h));
    }
}

__global__ void prep_all(const float* __restrict__ x,
                         const float* __restrict__ Wq, const float* __restrict__ Wk,
                         const float* __restrict__ Wv, const float* __restrict__ Wo)
{
    const int z = blockIdx.z, bx = blockIdx.x, by = blockIdx.y;
    if (z == 0)       transpose_split_body(Wq, g_wqt_h, g_wqt_l, C_DIM, C_DIM, bx, by);
    else if (z == 1)  transpose_split_body(Wo, g_wot_h, g_wot_l, C_DIM, C_DIM, bx, by);
    else if (z == 2) { if (bx < 16) transpose_split_body(Wk, g_wkt_h, g_wkt_l, C_DIM, NKV, bx, by); }
    else if (z == 3) { if (bx < 16) transpose_split_body(Wv, g_wvt_h, g_wvt_l, C_DIM, NKV, bx, by); }
    else {
        int tid = threadIdx.y * 32 + threadIdx.x;
        int i = ((z - 4) * 4096 + by * 64 + bx) * 256 + tid;
        float4 v = ((const float4*)x)[i];
        uint32_t h0, l0, h1, l1;
        split2(v.x, v.y, h0, l0);
        split2(v.z, v.w, h1, l1);
        ((uint2*)g_xh)[i] = make_uint2(h0, h1);
        ((uint2*)g_xl)[i] = make_uint2(l0, l1);
    }
}

// ---------------------------------------------------------------------------
// bf16x3 GEMM: 256x128 block, BK=64, 256 threads, 2-stage pipeline.
// Epilogues: 0=fp32, 1=split bf16, 2=RoPE+split, 3=RoPE+scale+split.
// ---------------------------------------------------------------------------
#define G2_AH 0
#define G2_AL 32768
#define G2_BH 65536
#define G2_BL 81920
#define G2_STAGE 98304
#define G2_SMEM  (2 * G2_STAGE)

__device__ __forceinline__ void g_load_stage(uint32_t dstbase,
    const __nv_bfloat16* __restrict__ Ah, const __nv_bfloat16* __restrict__ Al,
    const __nv_bfloat16* __restrict__ Bh, const __nv_bfloat16* __restrict__ Bl,
    int bm, int bn, int k0, int K, int tid)
{
    const int row = tid >> 3;
    const int c   = tid & 7;
    const uint32_t swc = (uint32_t)((c ^ (row & 7)) << 4);
#pragma unroll
    for (int jj = 0; jj < 8; jj++) {
        int r = row + 32 * jj;
        uint32_t so = (uint32_t)r * 128 + swc;
        size_t ga = (size_t)(bm + r) * K + k0 + c * 8;
        cp_async16(dstbase + G2_AH + so, Ah + ga);
        cp_async16(dstbase + G2_AL + so, Al + ga);
    }
#pragma unroll
    for (int jj = 0; jj < 4; jj++) {
        int r = row + 32 * jj;
        uint32_t so = (uint32_t)r * 128 + swc;
        size_t gb = (size_t)(bn + r) * K + k0 + c * 8;
        cp_async16(dstbase + G2_BH + so, Bh + gb);
        cp_async16(dstbase + G2_BL + so, Bl + gb);
    }
}

__device__ void gemm_body(
    const __nv_bfloat16* __restrict__ Ah, const __nv_bfloat16* __restrict__ Al,
    const __nv_bfloat16* __restrict__ Bh, const __nv_bfloat16* __restrict__ Bl,
    float* __restrict__ C, __nv_bfloat16* __restrict__ Ch, __nv_bfloat16* __restrict__ Cl,
    int epi, int M, int N, int K, int bxx, int byy)
{
    extern __shared__ char smg[];
    const int tid  = threadIdx.x;
    const int wid  = tid >> 5;
    const int lane = tid & 31;
    const int warp_m = wid & 3;
    const int warp_n = wid >> 2;
    const int bm = byy * 256;
    const int bn = bxx * 128;
    const uint32_t sbase = smem_u32(smg);

    const int ar  = (lane & 7) | (((lane >> 3) & 1) << 3);
    const int ag  = lane >> 4;
    const int ar7 = ar & 7;
    const int br  = (lane & 7) | ((lane >> 4) << 3);
    const int bg  = (lane >> 3) & 1;
    const int br7 = lane & 7;

    uint32_t a_ro[4], b_ro[4];
#pragma unroll
    for (int mi = 0; mi < 4; mi++)
        a_ro[mi] = (uint32_t)(warp_m * 64 + mi * 16 + ar) * 128 + G2_AH;
#pragma unroll
    for (int ng = 0; ng < 4; ng++)
        b_ro[ng] = (uint32_t)(warp_n * 64 + ng * 16 + br) * 128 + G2_BH;

    float acc[4][8][4];
#pragma unroll
    for (int mi = 0; mi < 4; mi++)
#pragma unroll
        for (int nf = 0; nf < 8; nf++)
#pragma unroll
            for (int e = 0; e < 4; e++) acc[mi][nf][e] = 0.0f;

    const int NK = K >> 6;

    g_load_stage(sbase, Ah, Al, Bh, Bl, bm, bn, 0, K, tid);
    cp_commit();

    for (int i = 0; i < NK; i++) {
        cp_wait<0>();
        __syncthreads();

        if (i + 1 < NK) {
            g_load_stage(sbase + ((i + 1) & 1) * G2_STAGE, Ah, Al, Bh, Bl,
                         bm, bn, (i + 1) * 64, K, tid);
            cp_commit();
        }

        const uint32_t stb = sbase + (i & 1) * G2_STAGE;
#pragma unroll
        for (int ks = 0; ks < 4; ks++) {
            const uint32_t cA = (uint32_t)(((ks * 2 + ag) ^ ar7) << 4);
            const uint32_t cB = (uint32_t)(((ks * 2 + bg) ^ br7) << 4);
            uint32_t ahi[4][4], alo[4][4];
#pragma unroll
            for (int mi = 0; mi < 4; mi++) {
                uint32_t ad = stb + a_ro[mi] + cA;
                LDMATRIX_X4(ahi[mi][0], ahi[mi][1], ahi[mi][2], ahi[mi][3], ad);
                LDMATRIX_X4(alo[mi][0], alo[mi][1], alo[mi][2], alo[mi][3], ad + 32768);
            }
            uint32_t bhi[4][4], blo[4][4];
#pragma unroll
            for (int ng = 0; ng < 4; ng++) {
                uint32_t bd = stb + b_ro[ng] + cB;
                LDMATRIX_X4(bhi[ng][0], bhi[ng][1], bhi[ng][2], bhi[ng][3], bd);
                LDMATRIX_X4(blo[ng][0], blo[ng][1], blo[ng][2], blo[ng][3], bd + 16384);
            }
#pragma unroll
            for (int mi = 0; mi < 4; mi++)
#pragma unroll
                for (int ng = 0; ng < 4; ng++) {
                    MMA_BF16(acc[mi][2*ng],   ahi[mi][0], ahi[mi][1], ahi[mi][2], ahi[mi][3], bhi[ng][0], bhi[ng][1]);
                    MMA_BF16(acc[mi][2*ng+1], ahi[mi][0], ahi[mi][1], ahi[mi][2], ahi[mi][3], bhi[ng][2], bhi[ng][3]);
                }
#pragma unroll
            for (int mi = 0; mi < 4; mi++)
#pragma unroll
                for (int ng = 0; ng < 4; ng++) {
                    MMA_BF16(acc[mi][2*ng],   ahi[mi][0], ahi[mi][1], ahi[mi][2], ahi[mi][3], blo[ng][0], blo[ng][1]);
                    MMA_BF16(acc[mi][2*ng+1], ahi[mi][0], ahi[mi][1], ahi[mi][2], ahi[mi][3], blo[ng][2], blo[ng][3]);
                }
#pragma unroll
            for (int mi = 0; mi < 4; mi++)
#pragma unroll
                for (int ng = 0; ng < 4; ng++) {
                    MMA_BF16(acc[mi][2*ng],   alo[mi][0], alo[mi][1], alo[mi][2], alo[mi][3], bhi[ng][0], bhi[ng][1]);
                    MMA_BF16(acc[mi][2*ng+1], alo[mi][0], alo[mi][1], alo[mi][2], alo[mi][3], bhi[ng][2], bhi[ng][3]);
                }
        }
        __syncthreads();
    }

    const int trow = lane >> 2;
    const int tcol = (lane & 3) << 1;

    if (epi <= 1) {
#pragma unroll
        for (int mi = 0; mi < 4; mi++) {
#pragma unroll
            for (int nf = 0; nf < 8; nf++) {
                int rg = bm + warp_m * 64 + mi * 16 + trow;
                int cg = bn + warp_n * 64 + nf * 8 + tcol;
                if (epi == 0) {
                    *(float2*)&C[(size_t)rg * N + cg]       = make_float2(acc[mi][nf][0], acc[mi][nf][1]);
                    *(float2*)&C[(size_t)(rg + 8) * N + cg] = make_float2(acc[mi][nf][2], acc[mi][nf][3]);
                } else {
                    uint32_t hh, ll;
                    split2(acc[mi][nf][0], acc[mi][nf][1], hh, ll);
                    *(uint32_t*)&Ch[(size_t)rg * N + cg] = hh;
                    *(uint32_t*)&Cl[(size_t)rg * N + cg] = ll;
                    split2(acc[mi][nf][2], acc[mi][nf][3], hh, ll);
                    *(uint32_t*)&Ch[(size_t)(rg + 8) * N + cg] = hh;
                    *(uint32_t*)&Cl[(size_t)(rg + 8) * N + cg] = ll;
                }
            }
        }
    } else {
        float* s_acc = (float*)smg;
#pragma unroll
        for (int mi = 0; mi < 4; mi++) {
#pragma unroll
            for (int nf = 0; nf < 8; nf++) {
                int rl = warp_m * 64 + mi * 16 + trow;
                int cl = warp_n * 64 + nf * 8 + tcol;
                *(float2*)&s_acc[rl * 132 + cl]       = make_float2(acc[mi][nf][0], acc[mi][nf][1]);
                *(float2*)&s_acc[(rl + 8) * 132 + cl] = make_float2(acc[mi][nf][2], acc[mi][nf][3]);
            }
        }
        __syncthreads();
        const float scq = (epi == 3) ? SCQ_CONST : 1.0f;
        const int rt = tid >> 5;
        const int j0 = (tid & 31) << 1;
#pragma unroll 4
        for (int it = 0; it < 32; it++) {
            int r  = it * 8 + rt;
            int gr = bm + r;
            float2 x0 = *(float2*)&s_acc[r * 132 + j0];
            float2 x1 = *(float2*)&s_acc[r * 132 + j0 + 64];
            float2 cv = *(const float2*)&g_cos[gr * 64 + j0];
            float2 sv = *(const float2*)&g_sin[gr * 64 + j0];
            float r0a = (x0.x * cv.x - x1.x * sv.x) * scq;
            float r0b = (x0.y * cv.y - x1.y * sv.y) * scq;
            float r1a = (x1.x * cv.x + x0.x * sv.x) * scq;
            float r1b = (x1.y * cv.y + x0.y * sv.y) * scq;
            size_t ob = (size_t)gr * N + bn + j0;
            uint32_t hh, ll;
            split2(r0a, r0b, hh, ll);
            *(uint32_t*)&Ch[ob] = hh;
            *(uint32_t*)&Cl[ob] = ll;
            split2(r1a, r1b, hh, ll);
            *(uint32_t*)&Ch[ob + 64] = hh;
            *(uint32_t*)&Cl[ob + 64] = ll;
        }
    }
}

// Packed grid (24, 16): bx<16 -> Q, 16..19 -> K, 20..23 -> V. No idle blocks.
__global__ __launch_bounds__(256)
void gemm_qkv(const __nv_bfloat16* __restrict__ xh, const __nv_bfloat16* __restrict__ xl)
{
    const int bx = blockIdx.x;
    if (bx < 16)
        gemm_body(xh, xl, g_wqt_h, g_wqt_l, nullptr, g_qsh, g_qsl, 3,
                  T_LEN, HQ * HD, C_DIM, bx, blockIdx.y);
    else if (bx < 20)
        gemm_body(xh, xl, g_wkt_h, g_wkt_l, nullptr, g_ksh, g_ksl, 2,
                  T_LEN, NKV, C_DIM, bx - 16, blockIdx.y);
    else
        gemm_body(xh, xl, g_wvt_h, g_wvt_l, nullptr, g_vsh, g_vsl, 1,
                  T_LEN, NKV, C_DIM, bx - 20, blockIdx.y);
}

__global__ __launch_bounds__(256)
void gemm_one(const __nv_bfloat16* Ah, const __nv_bfloat16* Al,
              const __nv_bfloat16* Bh, const __nv_bfloat16* Bl,
              float* C, int M, int N, int K)
{
    gemm_body(Ah, Al, Bh, Bl, C, nullptr, nullptr, 0, M, N, K, blockIdx.x, blockIdx.y);
}

// ---------------------------------------------------------------------------
// Flash attention: 128 queries x 64-key tiles, 256 threads (8 warps x 16 rows).
// Mask hoisted for interior tiles. Double-buffered cp.async K/V.
// ---------------------------------------------------------------------------
#define KVS   136
#define AR_SZ (64 * KVS * 2)            // 17408 B per array
#define A_KH  0
#define A_KL  AR_SZ
#define A_VH  (2 * AR_SZ)
#define A_VL  (3 * AR_SZ)
#define ATT_STAGE (4 * AR_SZ)           // 69632
#define ATT_SMEM  (2 * ATT_STAGE)       // 139264

__device__ __forceinline__ void attn_load_kv(uint32_t dstbase, int jb, int kvh, int tid)
{
#pragma unroll
    for (int i = 0; i < 4; i++) {
        int idx = tid + 256 * i;          // 0..1023
        int row = idx >> 4;               // 0..63
        int c16 = idx & 15;
        uint32_t so = (uint32_t)row * (KVS * 2) + c16 * 16;
        size_t g = (size_t)(jb + row) * NKV + kvh * HD + c16 * 8;
        cp_async16(dstbase + A_KH + so, g_ksh + g);
        cp_async16(dstbase + A_KL + so, g_ksl + g);
        cp_async16(dstbase + A_VH + so, g_vsh + g);
        cp_async16(dstbase + A_VL + so, g_vsl + g);
    }
}

__global__ __launch_bounds__(256)
void attn_tc_kernel(__nv_bfloat16* __restrict__ Yh, __nv_bfloat16* __restrict__ Yl)
{
    extern __shared__ char sma[];
    const uint32_t sbase = smem_u32(sma);

    const int qb  = blockIdx.x;           // 128-query block
    const int h   = blockIdx.y;
    const int kvh = h >> 2;
    const int tid  = threadIdx.x;
    const int wid  = tid >> 5;             // 0..7
    const int lane = tid & 31;
    const int trow = lane >> 2;
    const int tc2  = (lane & 3) << 1;
    const int q0    = qb * 128;
    const int qrow0 = q0 + wid * 16;

    // Q fragments (pre-scaled, pre-split)
    uint32_t qhi[8][4], qlo[8][4];
#pragma unroll
    for (int ks = 0; ks < 8; ks++) {
#pragma unroll
        for (int r = 0; r < 4; r++) {
            int row = qrow0 + trow + ((r & 1) << 3);
            int d = ks * 16 + ((r >> 1) << 3) + tc2;
            size_t o = (size_t)row * C_DIM + h * HD + d;
            qhi[ks][r] = *(const uint32_t*)&g_qsh[o];
            qlo[ks][r] = *(const uint32_t*)&g_qsl[o];
        }
    }

    float oacc[16][4];
#pragma unroll
    for (int nf = 0; nf < 16; nf++)
#pragma unroll
        for (int e = 0; e < 4; e++) oacc[nf][e] = 0.0f;
    float m2[2]   = { -1e30f, -1e30f };
    float lsum[2] = { 0.0f, 0.0f };

    int jmin = q0 - (WIN - 1);
    if (jmin < 0) jmin = 0;
    const int kb0 = jmin >> 6;
    const int kb1 = (q0 + 127) >> 6;

    // ldmatrix lane addressing
    const int krow    = (lane & 7) + ((lane >> 4) << 3);
    const int kcoloff = ((lane >> 3) & 1) << 3;
    const int vrow    = (lane & 7) + (((lane >> 3) & 1) << 3);
    const int vcoloff = (lane >> 4) << 3;

    const uint32_t kh_ro = (uint32_t)(krow * KVS + kcoloff) * 2;
    const uint32_t vh_ro = (uint32_t)(vrow * KVS + vcoloff) * 2;
    const uint32_t KROW16 = (uint32_t)(16 * KVS) * 2;

    attn_load_kv(sbase, kb0 * 64, kvh, tid);
    cp_commit();

    int s = 0;
    for (int kb = kb0; kb <= kb1; kb++) {
        const int jb = kb * 64;
        if (kb < kb1) {
            attn_load_kv(sbase + (s ^ 1) * ATT_STAGE, (kb + 1) * 64, kvh, tid);
            cp_commit();
            cp_wait<1>();
        } else {
            cp_wait<0>();
        }
        __syncthreads();

        const uint32_t stb = sbase + s * ATT_STAGE;
        const uint32_t kh_base = stb + A_KH + kh_ro;
        const uint32_t kl_base = stb + A_KL + kh_ro;
        const uint32_t vh_base = stb + A_VH + vh_ro;
        const uint32_t vl_base = stb + A_VL + vh_ro;

        // ---- S = Q K^T (8 fragments of 8 keys) ----
        float sacc[8][4];
#pragma unroll
        for (int f = 0; f < 8; f++)
#pragma unroll
            for (int e = 0; e < 4; e++) sacc[f][e] = 0.0f;

#pragma unroll
        for (int ks = 0; ks < 8; ks++) {
            uint32_t off = (uint32_t)(ks * 16) * 2;
#pragma unroll
            for (int g = 0; g < 4; g++) {
                uint32_t bh[4], bl[4];
                uint32_t ad = kh_base + off + g * KROW16;
                LDMATRIX_X4(bh[0], bh[1], bh[2], bh[3], ad);
                LDMATRIX_X4(bl[0], bl[1], bl[2], bl[3], ad + AR_SZ);
                const int f0 = 2 * g, f1 = 2 * g + 1;
                MMA_BF16(sacc[f0], qhi[ks][0], qhi[ks][1], qhi[ks][2], qhi[ks][3], bh[0], bh[1]);
                MMA_BF16(sacc[f1], qhi[ks][0], qhi[ks][1], qhi[ks][2], qhi[ks][3], bh[2], bh[3]);
                MMA_BF16(sacc[f0], qlo[ks][0], qlo[ks][1], qlo[ks][2], qlo[ks][3], bh[0], bh[1]);
                MMA_BF16(sacc[f1], qlo[ks][0], qlo[ks][1], qlo[ks][2], qlo[ks][3], bh[2], bh[3]);
                MMA_BF16(sacc[f0], qhi[ks][0], qhi[ks][1], qhi[ks][2], qhi[ks][3], bl[0], bl[1]);
                MMA_BF16(sacc[f1], qhi[ks][0], qhi[ks][1], qhi[ks][2], qhi[ks][3], bl[2], bl[3]);
            }
        }

        // ---- mask (hoisted: interior tiles skip it) ----
        const bool full = (jb >= q0 - (WIN - 128)) && (jb + 64 <= q0);
        if (!full) {
#pragma unroll
            for (int f = 0; f < 8; f++) {
                int j0 = jb + f * 8 + tc2;
#pragma unroll
                for (int e = 0; e < 4; e++) {
                    int j  = j0 + (e & 1);
                    int qi = qrow0 + trow + ((e >> 1) << 3);
                    bool ok = (j <= qi) && ((qi - j) < WIN);
                    if (!ok) sacc[f][e] = -1e30f;
                }
            }
        }

        // ---- online softmax (base-2; Q pre-scaled) ----
        float bm0 = -1e30f, bm1 = -1e30f;
#pragma unroll
        for (int f = 0; f < 8; f++) {
            bm0 = fmaxf(bm0, fmaxf(sacc[f][0], sacc[f][1]));
            bm1 = fmaxf(bm1, fmaxf(sacc[f][2], sacc[f][3]));
        }
        bm0 = fmaxf(bm0, __shfl_xor_sync(0xffffffffu, bm0, 1));
        bm0 = fmaxf(bm0, __shfl_xor_sync(0xffffffffu, bm0, 2));
        bm1 = fmaxf(bm1, __shfl_xor_sync(0xffffffffu, bm1, 1));
        bm1 = fmaxf(bm1, __shfl_xor_sync(0xffffffffu, bm1, 2));

        float mn0 = fmaxf(m2[0], bm0);
        float mn1 = fmaxf(m2[1], bm1);
        float mm0 = fmaxf(mn0, -1e20f);
        float mm1 = fmaxf(mn1, -1e20f);
        float f0 = exp2f(m2[0] - mm0);
        float f1 = exp2f(m2[1] - mm1);
        m2[0] = mn0; m2[1] = mn1;

        float ps0 = 0.0f, ps1 = 0.0f;
#pragma unroll
        for (int f = 0; f < 8; f++) {
            sacc[f][0] = exp2f(sacc[f][0] - mm0);
            sacc[f][1] = exp2f(sacc[f][1] - mm0);
            sacc[f][2] = exp2f(sacc[f][2] - mm1);
            sacc[f][3] = exp2f(sacc[f][3] - mm1);
            ps0 += sacc[f][0] + sacc[f][1];
            ps1 += sacc[f][2] + sacc[f][3];
        }
        ps0 += __shfl_xor_sync(0xffffffffu, ps0, 1);
        ps0 += __shfl_xor_sync(0xffffffffu, ps0, 2);
        ps1 += __shfl_xor_sync(0xffffffffu, ps1, 1);
        ps1 += __shfl_xor_sync(0xffffffffu, ps1, 2);
        lsum[0] = lsum[0] * f0 + ps0;
        lsum[1] = lsum[1] * f1 + ps1;

#pragma unroll
        for (int nf = 0; nf < 16; nf++) {
            oacc[nf][0] *= f0; oacc[nf][1] *= f0;
            oacc[nf][2] *= f1; oacc[nf][3] *= f1;
        }

        // ---- P fragments (hi/lo split): 4 k-groups of 16 keys ----
        uint32_t phi[4][4], plo[4][4];
#pragma unroll
        for (int kp = 0; kp < 4; kp++) {
            split2(sacc[2*kp][0],   sacc[2*kp][1],   phi[kp][0], plo[kp][0]);
            split2(sacc[2*kp][2],   sacc[2*kp][3],   phi[kp][1], plo[kp][1]);
            split2(sacc[2*kp+1][0], sacc[2*kp+1][1], phi[kp][2], plo[kp][2]);
            split2(sacc[2*kp+1][2], sacc[2*kp+1][3], phi[kp][3], plo[kp][3]);
        }

        // ---- O += P V ----
#pragma unroll
        for (int kp = 0; kp < 4; kp++) {
            uint32_t rowoff = (uint32_t)(kp * 16 * KVS) * 2;
#pragma unroll
            for (int ng = 0; ng < 8; ng++) {
                uint32_t coff = rowoff + (uint32_t)(ng * 16) * 2;
                uint32_t vh4[4], vl4[4];
                LDMATRIX_X4_T(vh4[0], vh4[1], vh4[2], vh4[3], vh_base + coff);
                LDMATRIX_X4_T(vl4[0], vl4[1], vl4[2], vl4[3], vl_base + coff);
                MMA_BF16(oacc[2*ng],   phi[kp][0], phi[kp][1], phi[kp][2], phi[kp][3], vh4[0], vh4[1]);
                MMA_BF16(oacc[2*ng+1], phi[kp][0], phi[kp][1], phi[kp][2], phi[kp][3], vh4[2], vh4[3]);
                MMA_BF16(oacc[2*ng],   plo[kp][0], plo[kp][1], plo[kp][2], plo[kp][3], vh4[0], vh4[1]);
                MMA_BF16(oacc[2*ng+1], plo[kp][0], plo[kp][1], plo[kp][2], plo[kp][3], vh4[2], vh4[3]);
                MMA_BF16(oacc[2*ng],   phi[kp][0], phi[kp][1], phi[kp][2], phi[kp][3], vl4[0], vl4[1]);
                MMA_BF16(oacc[2*ng+1], phi[kp][0], phi[kp][1], phi[kp][2], phi[kp][3], vl4[2], vl4[3]);
            }
        }
        __syncthreads();
        s ^= 1;
    }

    // epilogue: normalize, split, write bf16 Y
    float il0 = 1.0f / lsum[0];
    float il1 = 1.0f / lsum[1];
    const int row0 = qrow0 + trow;
#pragma unroll
    for (int nf = 0; nf < 16; nf++) {
        int col = h * HD + nf * 8 + tc2;
        uint32_t hh, ll;
        split2(oacc[nf][0] * il0, oacc[nf][1] * il0, hh, ll);
        *(uint32_t*)&Yh[(size_t)row0 * C_DIM + col] = hh;
        *(uint32_t*)&Yl[(size_t)row0 * C_DIM + col] = ll;
        split2(oacc[nf][2] * il1, oacc[nf][3] * il1, hh, ll);
        *(uint32_t*)&Yh[(size_t)(row0 + 8) * C_DIM + col] = hh;
        *(uint32_t*)&Yl[(size_t)(row0 + 8) * C_DIM + col] = ll;
    }
}

// ---------------------------------------------------------------------------
// Launch: 1 rope_table, 2 prep_all, 3 gemm_qkv, 4 attention (profiled), 5 Wo.
// ---------------------------------------------------------------------------
extern "C" void kernel_launch(void* const* d_in, const int* in_sizes, int n_in,
                              void* d_out, int out_size)
{
    const float* x  = (const float*)d_in[0];
    const float* Wq = (const float*)d_in[1];
    const float* Wk = (const float*)d_in[2];
    const float* Wv = (const float*)d_in[3];
    const float* Wo = (const float*)d_in[4];
    float* out = (float*)d_out;

    __nv_bfloat16 *xh, *xl, *yh, *yl, *woh, *wol;
    cudaGetSymbolAddress((void**)&xh, g_xh);
    cudaGetSymbolAddress((void**)&xl, g_xl);
    cudaGetSymbolAddress((void**)&yh, g_yh);
    cudaGetSymbolAddress((void**)&yl, g_yl);
    cudaGetSymbolAddress((void**)&woh, g_wot_h);
    cudaGetSymbolAddress((void**)&wol, g_wot_l);

    static bool attr_done = false;
    if (!attr_done) {
        cudaFuncSetAttribute(gemm_one, cudaFuncAttributeMaxDynamicSharedMemorySize, G2_SMEM);
        cudaFuncSetAttribute(gemm_qkv, cudaFuncAttributeMaxDynamicSharedMemorySize, G2_SMEM);
        cudaFuncSetAttribute(attn_tc_kernel, cudaFuncAttributeMaxDynamicSharedMemorySize, ATT_SMEM);
        attr_done = true;
    }

    // 1: RoPE table
    rope_table_kernel<<<(T_LEN * 64) / 256, 256>>>();
    // 2: all prep
    prep_all<<<dim3(64, 64, 6), dim3(32, 8)>>>(x, Wq, Wk, Wv, Wo);
    // 3: Q/K/V projections (packed grid, fused RoPE/split epilogues)
    gemm_qkv<<<dim3(24, T_LEN / 256), 256, G2_SMEM>>>(xh, xl);
    // 4: attention (profiled slot)
    attn_tc_kernel<<<dim3(T_LEN / 128, HQ), 256, ATT_SMEM>>>(yh, yl);
    // 5: output projection
    gemm_one<<<dim3(C_DIM / 128, T_LEN / 256), 256, G2_SMEM>>>(yh, yl, woh, wol, out, T_LEN, C_DIM, C_DIM);
}

// round 12
// speedup vs baseline: 1.0307x; 1.0307x over previous
#include <cuda_runtime.h>
#include <cuda_bf16.h>
#include <math.h>
#include <float.h>
#include <stdint.h>

// Problem constants
#define T_LEN   4096
#define C_DIM   2048
#define HQ      16
#define HKV     4
#define HD      128
#define WIN     1024
#define NKV     (HKV * HD)     // 512

// fp32 scratch
__device__ float g_Q[T_LEN * HQ * HD];
__device__ float g_K[T_LEN * NKV];
__device__ float g_cos[T_LEN * 64];
__device__ float g_sin[T_LEN * 64];

// bf16 split operands
__device__ __nv_bfloat16 g_xh[T_LEN * C_DIM],  g_xl[T_LEN * C_DIM];
__device__ __nv_bfloat16 g_yh[T_LEN * C_DIM],  g_yl[T_LEN * C_DIM];
__device__ __nv_bfloat16 g_qsh[T_LEN * C_DIM], g_qsl[T_LEN * C_DIM];
__device__ __nv_bfloat16 g_ksh[T_LEN * NKV],   g_ksl[T_LEN * NKV];
__device__ __nv_bfloat16 g_vsh[T_LEN * NKV],   g_vsl[T_LEN * NKV];
__device__ __nv_bfloat16 g_wqt_h[C_DIM * C_DIM], g_wqt_l[C_DIM * C_DIM];
__device__ __nv_bfloat16 g_wkt_h[NKV * C_DIM],   g_wkt_l[NKV * C_DIM];
__device__ __nv_bfloat16 g_wvt_h[NKV * C_DIM],   g_wvt_l[NKV * C_DIM];
__device__ __nv_bfloat16 g_wot_h[C_DIM * C_DIM], g_wot_l[C_DIM * C_DIM];

// ---------------------------------------------------------------------------
// helpers
// ---------------------------------------------------------------------------
__device__ __forceinline__ uint32_t smem_u32(const void* p) {
    return (uint32_t)__cvta_generic_to_shared(p);
}

__device__ __forceinline__ void split2(float a, float b, uint32_t& hi, uint32_t& lo) {
    __nv_bfloat16 ah = __float2bfloat16_rn(a);
    __nv_bfloat16 bh = __float2bfloat16_rn(b);
    __nv_bfloat162 h(ah, bh);
    hi = *(uint32_t*)&h;
    __nv_bfloat162 l(__float2bfloat16_rn(a - __bfloat162float(ah)),
                     __float2bfloat16_rn(b - __bfloat162float(bh)));
    lo = *(uint32_t*)&l;
}

#define LDMATRIX_X4(R0,R1,R2,R3,ADDR) \
    asm volatile("ldmatrix.sync.aligned.m8n8.x4.shared.b16 {%0,%1,%2,%3}, [%4];" \
        : "=r"(R0), "=r"(R1), "=r"(R2), "=r"(R3) : "r"(ADDR))

#define LDMATRIX_X4_T(R0,R1,R2,R3,ADDR) \
    asm volatile("ldmatrix.sync.aligned.m8n8.x4.trans.shared.b16 {%0,%1,%2,%3}, [%4];" \
        : "=r"(R0), "=r"(R1), "=r"(R2), "=r"(R3) : "r"(ADDR))

#define MMA_BF16(D, A0,A1,A2,A3, B0,B1) \
    asm volatile("mma.sync.aligned.m16n8k16.row.col.f32.bf16.bf16.f32 " \
        "{%0,%1,%2,%3}, {%4,%5,%6,%7}, {%8,%9}, {%0,%1,%2,%3};" \
        : "+f"((D)[0]), "+f"((D)[1]), "+f"((D)[2]), "+f"((D)[3]) \
        : "r"(A0), "r"(A1), "r"(A2), "r"(A3), "r"(B0), "r"(B1))

__device__ __forceinline__ void cp_async16(uint32_t dst, const void* src) {
    asm volatile("cp.async.cg.shared.global [%0], [%1], 16;" :: "r"(dst), "l"(src));
}
__device__ __forceinline__ void cp_commit() {
    asm volatile("cp.async.commit_group;" ::: "memory");
}
template <int NN> __device__ __forceinline__ void cp_wait() {
    asm volatile("cp.async.wait_group %0;" :: "n"(NN) : "memory");
}

// ---------------------------------------------------------------------------
// Prep kernels
// ---------------------------------------------------------------------------
__global__ void split_f32_kernel(const float* __restrict__ src,
                                 __nv_bfloat16* __restrict__ hi,
                                 __nv_bfloat16* __restrict__ lo, int n4)
{
    int i = blockIdx.x * blockDim.x + threadIdx.x;
    if (i >= n4) return;
    float4 v = ((const float4*)src)[i];
    uint32_t h0, l0, h1, l1;
    split2(v.x, v.y, h0, l0);
    split2(v.z, v.w, h1, l1);
    ((uint2*)hi)[i] = make_uint2(h0, h1);
    ((uint2*)lo)[i] = make_uint2(l0, l1);
}

__device__ __forceinline__ void transpose_split_body(
    const float* __restrict__ W, __nv_bfloat16* __restrict__ Th,
    __nv_bfloat16* __restrict__ Tl, int Kd, int Nd)
{
    __shared__ float tile[32][33];
    const int bx = blockIdx.x;
    const int by = blockIdx.y;
    const int x = threadIdx.x;
    const int y = threadIdx.y;
#pragma unroll
    for (int j = 0; j < 32; j += 8)
        tile[y + j][x] = W[(size_t)(by * 32 + y + j) * Nd + bx * 32 + x];
    __syncthreads();
#pragma unroll
    for (int j = 0; j < 32; j += 8) {
        float v = tile[x][y + j];
        __nv_bfloat16 h = __float2bfloat16_rn(v);
        size_t o = (size_t)(bx * 32 + y + j) * Kd + by * 32 + x;
        Th[o] = h;
        Tl[o] = __float2bfloat16_rn(v - __bfloat162float(h));
    }
}

__global__ void transpose_qo_kernel(const float* __restrict__ Wq, const float* __restrict__ Wo)
{
    if (blockIdx.z == 0) transpose_split_body(Wq, g_wqt_h, g_wqt_l, C_DIM, C_DIM);
    else                 transpose_split_body(Wo, g_wot_h, g_wot_l, C_DIM, C_DIM);
}

__global__ void transpose_kv_kernel(const float* __restrict__ Wk, const float* __restrict__ Wv)
{
    if (blockIdx.z == 0) transpose_split_body(Wk, g_wkt_h, g_wkt_l, C_DIM, NKV);
    else                 transpose_split_body(Wv, g_wvt_h, g_wvt_l, C_DIM, NKV);
}

// ---------------------------------------------------------------------------
// bf16x3 GEMM: C[M,N] = A[M,K] * B[N,K]^T, pre-split bf16 operands.
// 256x128 block tile, BK=64, 256 threads (8 warps, 64x64 warp tiles),
// 2-stage cp.async pipeline. Optional split-bf16 output.
// ---------------------------------------------------------------------------
#define G2_AH 0
#define G2_AL 32768
#define G2_BH 65536
#define G2_BL 81920
#define G2_STAGE 98304
#define G2_SMEM  (2 * G2_STAGE)   // 196608

__device__ __forceinline__ void g_load_stage(uint32_t dstbase,
    const __nv_bfloat16* __restrict__ Ah, const __nv_bfloat16* __restrict__ Al,
    const __nv_bfloat16* __restrict__ Bh, const __nv_bfloat16* __restrict__ Bl,
    int bm, int bn, int k0, int K, int tid)
{
    const int row = tid >> 3;
    const int c   = tid & 7;
    const uint32_t swc = (uint32_t)((c ^ (row & 7)) << 4);
#pragma unroll
    for (int jj = 0; jj < 8; jj++) {
        int r = row + 32 * jj;
        uint32_t so = (uint32_t)r * 128 + swc;
        size_t ga = (size_t)(bm + r) * K + k0 + c * 8;
        cp_async16(dstbase + G2_AH + so, Ah + ga);
        cp_async16(dstbase + G2_AL + so, Al + ga);
    }
#pragma unroll
    for (int jj = 0; jj < 4; jj++) {
        int r = row + 32 * jj;
        uint32_t so = (uint32_t)r * 128 + swc;
        size_t gb = (size_t)(bn + r) * K + k0 + c * 8;
        cp_async16(dstbase + G2_BH + so, Bh + gb);
        cp_async16(dstbase + G2_BL + so, Bl + gb);
    }
}

__device__ void gemm_body(
    const __nv_bfloat16* __restrict__ Ah, const __nv_bfloat16* __restrict__ Al,
    const __nv_bfloat16* __restrict__ Bh, const __nv_bfloat16* __restrict__ Bl,
    float* __restrict__ C, __nv_bfloat16* __restrict__ Ch, __nv_bfloat16* __restrict__ Cl,
    int splitout, int M, int N, int K, int bxx, int byy)
{
    extern __shared__ char smg[];
    const int tid  = threadIdx.x;
    const int wid  = tid >> 5;
    const int lane = tid & 31;
    const int warp_m = wid & 3;
    const int warp_n = wid >> 2;
    const int bm = byy * 256;
    const int bn = bxx * 128;
    const uint32_t sbase = smem_u32(smg);

    const int ar  = (lane & 7) | (((lane >> 3) & 1) << 3);
    const int ag  = lane >> 4;
    const int ar7 = ar & 7;
    const int br  = (lane & 7) | ((lane >> 4) << 3);
    const int bg  = (lane >> 3) & 1;
    const int br7 = lane & 7;

    uint32_t a_ro[4], b_ro[4];
#pragma unroll
    for (int mi = 0; mi < 4; mi++)
        a_ro[mi] = (uint32_t)(warp_m * 64 + mi * 16 + ar) * 128 + G2_AH;
#pragma unroll
    for (int ng = 0; ng < 4; ng++)
        b_ro[ng] = (uint32_t)(warp_n * 64 + ng * 16 + br) * 128 + G2_BH;

    float acc[4][8][4];
#pragma unroll
    for (int mi = 0; mi < 4; mi++)
#pragma unroll
        for (int nf = 0; nf < 8; nf++)
#pragma unroll
            for (int e = 0; e < 4; e++) acc[mi][nf][e] = 0.0f;

    const int NK = K >> 6;

    g_load_stage(sbase, Ah, Al, Bh, Bl, bm, bn, 0, K, tid);
    cp_commit();

    for (int i = 0; i < NK; i++) {
        cp_wait<0>();
        __syncthreads();

        if (i + 1 < NK) {
            g_load_stage(sbase + ((i + 1) & 1) * G2_STAGE, Ah, Al, Bh, Bl,
                         bm, bn, (i + 1) * 64, K, tid);
            cp_commit();
        }

        const uint32_t stb = sbase + (i & 1) * G2_STAGE;
#pragma unroll
        for (int ks = 0; ks < 4; ks++) {
            const uint32_t cA = (uint32_t)(((ks * 2 + ag) ^ ar7) << 4);
            const uint32_t cB = (uint32_t)(((ks * 2 + bg) ^ br7) << 4);
            uint32_t ahi[4][4], alo[4][4];
#pragma unroll
            for (int mi = 0; mi < 4; mi++) {
                uint32_t ad = stb + a_ro[mi] + cA;
                LDMATRIX_X4(ahi[mi][0], ahi[mi][1], ahi[mi][2], ahi[mi][3], ad);
                LDMATRIX_X4(alo[mi][0], alo[mi][1], alo[mi][2], alo[mi][3], ad + 32768);
            }
            uint32_t bhi[4][4], blo[4][4];
#pragma unroll
            for (int ng = 0; ng < 4; ng++) {
                uint32_t bd = stb + b_ro[ng] + cB;
                LDMATRIX_X4(bhi[ng][0], bhi[ng][1], bhi[ng][2], bhi[ng][3], bd);
                LDMATRIX_X4(blo[ng][0], blo[ng][1], blo[ng][2], blo[ng][3], bd + 16384);
            }
#pragma unroll
            for (int mi = 0; mi < 4; mi++)
#pragma unroll
                for (int ng = 0; ng < 4; ng++) {
                    MMA_BF16(acc[mi][2*ng],   ahi[mi][0], ahi[mi][1], ahi[mi][2], ahi[mi][3], bhi[ng][0], bhi[ng][1]);
                    MMA_BF16(acc[mi][2*ng+1], ahi[mi][0], ahi[mi][1], ahi[mi][2], ahi[mi][3], bhi[ng][2], bhi[ng][3]);
                }
#pragma unroll
            for (int mi = 0; mi < 4; mi++)
#pragma unroll
                for (int ng = 0; ng < 4; ng++) {
                    MMA_BF16(acc[mi][2*ng],   ahi[mi][0], ahi[mi][1], ahi[mi][2], ahi[mi][3], blo[ng][0], blo[ng][1]);
                    MMA_BF16(acc[mi][2*ng+1], ahi[mi][0], ahi[mi][1], ahi[mi][2], ahi[mi][3], blo[ng][2], blo[ng][3]);
                }
#pragma unroll
            for (int mi = 0; mi < 4; mi++)
#pragma unroll
                for (int ng = 0; ng < 4; ng++) {
                    MMA_BF16(acc[mi][2*ng],   alo[mi][0], alo[mi][1], alo[mi][2], alo[mi][3], bhi[ng][0], bhi[ng][1]);
                    MMA_BF16(acc[mi][2*ng+1], alo[mi][0], alo[mi][1], alo[mi][2], alo[mi][3], bhi[ng][2], bhi[ng][3]);
                }
        }
        __syncthreads();
    }

    const int trow = lane >> 2;
    const int tcol = (lane & 3) << 1;
#pragma unroll
    for (int mi = 0; mi < 4; mi++) {
#pragma unroll
        for (int nf = 0; nf < 8; nf++) {
            int rg = bm + warp_m * 64 + mi * 16 + trow;
            int cg = bn + warp_n * 64 + nf * 8 + tcol;
            if (!splitout) {
                *(float2*)&C[(size_t)rg * N + cg]       = make_float2(acc[mi][nf][0], acc[mi][nf][1]);
                *(float2*)&C[(size_t)(rg + 8) * N + cg] = make_float2(acc[mi][nf][2], acc[mi][nf][3]);
            } else {
                uint32_t hh, ll;
                split2(acc[mi][nf][0], acc[mi][nf][1], hh, ll);
                *(uint32_t*)&Ch[(size_t)rg * N + cg] = hh;
                *(uint32_t*)&Cl[(size_t)rg * N + cg] = ll;
                split2(acc[mi][nf][2], acc[mi][nf][3], hh, ll);
                *(uint32_t*)&Ch[(size_t)(rg + 8) * N + cg] = hh;
                *(uint32_t*)&Cl[(size_t)(rg + 8) * N + cg] = ll;
            }
        }
    }
}

__global__ __launch_bounds__(256)
void gemm_one(const __nv_bfloat16* Ah, const __nv_bfloat16* Al,
              const __nv_bfloat16* Bh, const __nv_bfloat16* Bl,
              float* C, int M, int N, int K)
{
    gemm_body(Ah, Al, Bh, Bl, C, nullptr, nullptr, 0, M, N, K, blockIdx.x, blockIdx.y);
}

__global__ __launch_bounds__(256)
void gemm_kv(const __nv_bfloat16* Ah, const __nv_bfloat16* Al, float* Kout)
{
    if (blockIdx.z == 0)
        gemm_body(Ah, Al, g_wkt_h, g_wkt_l, Kout, nullptr, nullptr, 0,
                  T_LEN, NKV, C_DIM, blockIdx.x, blockIdx.y);
    else
        gemm_body(Ah, Al, g_wvt_h, g_wvt_l, nullptr, g_vsh, g_vsl, 1,
                  T_LEN, NKV, C_DIM, blockIdx.x, blockIdx.y);
}

// ---------------------------------------------------------------------------
// RoPE: fp64 exp for invf (bit-compat), fp32 sincosf on the fp32 angle.
// ---------------------------------------------------------------------------
__global__ void rope_table_kernel()
{
    __shared__ float s_invf[64];
    if (threadIdx.x < 64) {
        double e = exp(-(double)threadIdx.x * (log(10000.0) / 64.0));
        s_invf[threadIdx.x] = (float)e;
    }
    __syncthreads();
    int idx = blockIdx.x * blockDim.x + threadIdx.x;
    if (idx >= T_LEN * 64) return;
    int t = idx >> 6;
    int j = idx & 63;
    float ang = (float)t * s_invf[j];
    float s, c;
    sincosf(ang, &s, &c);
    g_cos[idx] = c;
    g_sin[idx] = s;
}

// RoPE apply + split, 2 j-values per thread. Q scaled by 1/sqrt(128)*log2(e).
__global__ void rope_apply_split_kernel(const float* __restrict__ Q,
                                        const float* __restrict__ K)
{
    const float SCQ = (float)(0.08838834764831845 * 1.4426950408889634);
    const int NQ2 = T_LEN * HQ * 32;
    int idx = blockIdx.x * blockDim.x + threadIdx.x;
    if (idx < NQ2) {
        int t = idx >> 9;
        int rem = idx & 511;
        int h = rem >> 5;
        int j2 = (rem & 31) << 1;
        size_t o = (size_t)t * C_DIM + h * HD;
        const float* p = Q + o;
        float2 x0 = *(const float2*)(p + j2);
        float2 x1 = *(const float2*)(p + j2 + 64);
        float2 cv = *(const float2*)(g_cos + t * 64 + j2);
        float2 sv = *(const float2*)(g_sin + t * 64 + j2);
        float r0a = (x0.x * cv.x - x1.x * sv.x) * SCQ;
        float r0b = (x0.y * cv.y - x1.y * sv.y) * SCQ;
        float r1a = (x1.x * cv.x + x0.x * sv.x) * SCQ;
        float r1b = (x1.y * cv.y + x0.y * sv.y) * SCQ;
        uint32_t hh, ll;
        split2(r0a, r0b, hh, ll);
        *(uint32_t*)&g_qsh[o + j2] = hh;
        *(uint32_t*)&g_qsl[o + j2] = ll;
        split2(r1a, r1b, hh, ll);
        *(uint32_t*)&g_qsh[o + j2 + 64] = hh;
        *(uint32_t*)&g_qsl[o + j2 + 64] = ll;
    } else {
        int i2 = idx - NQ2;
        int t = i2 >> 7;
        int rem = i2 & 127;
        int h = rem >> 5;
        int j2 = (rem & 31) << 1;
        size_t o = (size_t)t * NKV + h * HD;
        const float* p = K + o;
        float2 x0 = *(const float2*)(p + j2);
        float2 x1 = *(const float2*)(p + j2 + 64);
        float2 cv = *(const float2*)(g_cos + t * 64 + j2);
        float2 sv = *(const float2*)(g_sin + t * 64 + j2);
        float r0a = x0.x * cv.x - x1.x * sv.x;
        float r0b = x0.y * cv.y - x1.y * sv.y;
        float r1a = x1.x * cv.x + x0.x * sv.x;
        float r1b = x1.y * cv.y + x0.y * sv.y;
        uint32_t hh, ll;
        split2(r0a, r0b, hh, ll);
        *(uint32_t*)&g_ksh[o + j2] = hh;
        *(uint32_t*)&g_ksl[o + j2] = ll;
        split2(r1a, r1b, hh, ll);
        *(uint32_t*)&g_ksh[o + j2 + 64] = hh;
        *(uint32_t*)&g_ksl[o + j2 + 64] = ll;
    }
}

// ---------------------------------------------------------------------------
// Flash attention: 128 queries x 64-key tiles, 256 threads (8 warps x 16 rows).
// Mask hoisted for interior tiles. Double-buffered cp.async K/V.
// ---------------------------------------------------------------------------
#define KVS   136
#define AR_SZ (64 * KVS * 2)            // 17408 B per array
#define A_KH  0
#define A_KL  AR_SZ
#define A_VH  (2 * AR_SZ)
#define A_VL  (3 * AR_SZ)
#define ATT_STAGE (4 * AR_SZ)           // 69632
#define ATT_SMEM  (2 * ATT_STAGE)       // 139264

__device__ __forceinline__ void attn_load_kv(uint32_t dstbase, int jb, int kvh, int tid)
{
#pragma unroll
    for (int i = 0; i < 4; i++) {
        int idx = tid + 256 * i;
        int row = idx >> 4;
        int c16 = idx & 15;
        uint32_t so = (uint32_t)row * (KVS * 2) + c16 * 16;
        size_t g = (size_t)(jb + row) * NKV + kvh * HD + c16 * 8;
        cp_async16(dstbase + A_KH + so, g_ksh + g);
        cp_async16(dstbase + A_KL + so, g_ksl + g);
        cp_async16(dstbase + A_VH + so, g_vsh + g);
        cp_async16(dstbase + A_VL + so, g_vsl + g);
    }
}

__global__ __launch_bounds__(256)
void attn_tc_kernel(__nv_bfloat16* __restrict__ Yh, __nv_bfloat16* __restrict__ Yl)
{
    extern __shared__ char sma[];
    const uint32_t sbase = smem_u32(sma);

    const int qb  = blockIdx.x;
    const int h   = blockIdx.y;
    const int kvh = h >> 2;
    const int tid  = threadIdx.x;
    const int wid  = tid >> 5;
    const int lane = tid & 31;
    const int trow = lane >> 2;
    const int tc2  = (lane & 3) << 1;
    const int q0    = qb * 128;
    const int qrow0 = q0 + wid * 16;

    uint32_t qhi[8][4], qlo[8][4];
#pragma unroll
    for (int ks = 0; ks < 8; ks++) {
#pragma unroll
        for (int r = 0; r < 4; r++) {
            int row = qrow0 + trow + ((r & 1) << 3);
            int d = ks * 16 + ((r >> 1) << 3) + tc2;
            size_t o = (size_t)row * C_DIM + h * HD + d;
            qhi[ks][r] = *(const uint32_t*)&g_qsh[o];
            qlo[ks][r] = *(const uint32_t*)&g_qsl[o];
        }
    }

    float oacc[16][4];
#pragma unroll
    for (int nf = 0; nf < 16; nf++)
#pragma unroll
        for (int e = 0; e < 4; e++) oacc[nf][e] = 0.0f;
    float m2[2]   = { -1e30f, -1e30f };
    float lsum[2] = { 0.0f, 0.0f };

    int jmin = q0 - (WIN - 1);
    if (jmin < 0) jmin = 0;
    const int kb0 = jmin >> 6;
    const int kb1 = (q0 + 127) >> 6;

    const int krow    = (lane & 7) + ((lane >> 4) << 3);
    const int kcoloff = ((lane >> 3) & 1) << 3;
    const int vrow    = (lane & 7) + (((lane >> 3) & 1) << 3);
    const int vcoloff = (lane >> 4) << 3;

    const uint32_t kh_ro = (uint32_t)(krow * KVS + kcoloff) * 2;
    const uint32_t vh_ro = (uint32_t)(vrow * KVS + vcoloff) * 2;
    const uint32_t KROW16 = (uint32_t)(16 * KVS) * 2;

    attn_load_kv(sbase, kb0 * 64, kvh, tid);
    cp_commit();

    int s = 0;
    for (int kb = kb0; kb <= kb1; kb++) {
        const int jb = kb * 64;
        if (kb < kb1) {
            attn_load_kv(sbase + (s ^ 1) * ATT_STAGE, (kb + 1) * 64, kvh, tid);
            cp_commit();
            cp_wait<1>();
        } else {
            cp_wait<0>();
        }
        __syncthreads();

        const uint32_t stb = sbase + s * ATT_STAGE;
        const uint32_t kh_base = stb + A_KH + kh_ro;
        const uint32_t vh_base = stb + A_VH + vh_ro;
        const uint32_t vl_base = stb + A_VL + vh_ro;

        float sacc[8][4];
#pragma unroll
        for (int f = 0; f < 8; f++)
#pragma unroll
            for (int e = 0; e < 4; e++) sacc[f][e] = 0.0f;

#pragma unroll
        for (int ks = 0; ks < 8; ks++) {
            uint32_t off = (uint32_t)(ks * 16) * 2;
#pragma unroll
            for (int g = 0; g < 4; g++) {
                uint32_t bh[4], bl[4];
                uint32_t ad = kh_base + off + g * KROW16;
                LDMATRIX_X4(bh[0], bh[1], bh[2], bh[3], ad);
                LDMATRIX_X4(bl[0], bl[1], bl[2], bl[3], ad + AR_SZ);
                const int f0 = 2 * g, f1 = 2 * g + 1;
                MMA_BF16(sacc[f0], qhi[ks][0], qhi[ks][1], qhi[ks][2], qhi[ks][3], bh[0], bh[1]);
                MMA_BF16(sacc[f1], qhi[ks][0], qhi[ks][1], qhi[ks][2], qhi[ks][3], bh[2], bh[3]);
                MMA_BF16(sacc[f0], qlo[ks][0], qlo[ks][1], qlo[ks][2], qlo[ks][3], bh[0], bh[1]);
                MMA_BF16(sacc[f1], qlo[ks][0], qlo[ks][1], qlo[ks][2], qlo[ks][3], bh[2], bh[3]);
                MMA_BF16(sacc[f0], qhi[ks][0], qhi[ks][1], qhi[ks][2], qhi[ks][3], bl[0], bl[1]);
                MMA_BF16(sacc[f1], qhi[ks][0], qhi[ks][1], qhi[ks][2], qhi[ks][3], bl[2], bl[3]);
            }
        }

        const bool full = (jb >= q0 - (WIN - 128)) && (jb + 64 <= q0);
        if (!full) {
#pragma unroll
            for (int f = 0; f < 8; f++) {
                int j0 = jb + f * 8 + tc2;
#pragma unroll
                for (int e = 0; e < 4; e++) {
                    int j  = j0 + (e & 1);
                    int qi = qrow0 + trow + ((e >> 1) << 3);
                    bool ok = (j <= qi) && ((qi - j) < WIN);
                    if (!ok) sacc[f][e] = -1e30f;
                }
            }
        }

        float bm0 = -1e30f, bm1 = -1e30f;
#pragma unroll
        for (int f = 0; f < 8; f++) {
            bm0 = fmaxf(bm0, fmaxf(sacc[f][0], sacc[f][1]));
            bm1 = fmaxf(bm1, fmaxf(sacc[f][2], sacc[f][3]));
        }
        bm0 = fmaxf(bm0, __shfl_xor_sync(0xffffffffu, bm0, 1));
        bm0 = fmaxf(bm0, __shfl_xor_sync(0xffffffffu, bm0, 2));
        bm1 = fmaxf(bm1, __shfl_xor_sync(0xffffffffu, bm1, 1));
        bm1 = fmaxf(bm1, __shfl_xor_sync(0xffffffffu, bm1, 2));

        float mn0 = fmaxf(m2[0], bm0);
        float mn1 = fmaxf(m2[1], bm1);
        float mm0 = fmaxf(mn0, -1e20f);
        float mm1 = fmaxf(mn1, -1e20f);
        float f0 = exp2f(m2[0] - mm0);
        float f1 = exp2f(m2[1] - mm1);
        m2[0] = mn0; m2[1] = mn1;

        float ps0 = 0.0f, ps1 = 0.0f;
#pragma unroll
        for (int f = 0; f < 8; f++) {
            sacc[f][0] = exp2f(sacc[f][0] - mm0);
            sacc[f][1] = exp2f(sacc[f][1] - mm0);
            sacc[f][2] = exp2f(sacc[f][2] - mm1);
            sacc[f][3] = exp2f(sacc[f][3] - mm1);
            ps0 += sacc[f][0] + sacc[f][1];
            ps1 += sacc[f][2] + sacc[f][3];
        }
        ps0 += __shfl_xor_sync(0xffffffffu, ps0, 1);
        ps0 += __shfl_xor_sync(0xffffffffu, ps0, 2);
        ps1 += __shfl_xor_sync(0xffffffffu, ps1, 1);
        ps1 += __shfl_xor_sync(0xffffffffu, ps1, 2);
        lsum[0] = lsum[0] * f0 + ps0;
        lsum[1] = lsum[1] * f1 + ps1;

#pragma unroll
        for (int nf = 0; nf < 16; nf++) {
            oacc[nf][0] *= f0; oacc[nf][1] *= f0;
            oacc[nf][2] *= f1; oacc[nf][3] *= f1;
        }

        uint32_t phi[4][4], plo[4][4];
#pragma unroll
        for (int kp = 0; kp < 4; kp++) {
            split2(sacc[2*kp][0],   sacc[2*kp][1],   phi[kp][0], plo[kp][0]);
            split2(sacc[2*kp][2],   sacc[2*kp][3],   phi[kp][1], plo[kp][1]);
            split2(sacc[2*kp+1][0], sacc[2*kp+1][1], phi[kp][2], plo[kp][2]);
            split2(sacc[2*kp+1][2], sacc[2*kp+1][3], phi[kp][3], plo[kp][3]);
        }

#pragma unroll
        for (int kp = 0; kp < 4; kp++) {
            uint32_t rowoff = (uint32_t)(kp * 16 * KVS) * 2;
#pragma unroll
            for (int ng = 0; ng < 8; ng++) {
                uint32_t coff = rowoff + (uint32_t)(ng * 16) * 2;
                uint32_t vh4[4], vl4[4];
                LDMATRIX_X4_T(vh4[0], vh4[1], vh4[2], vh4[3], vh_base + coff);
                LDMATRIX_X4_T(vl4[0], vl4[1], vl4[2], vl4[3], vl_base + coff);
                MMA_BF16(oacc[2*ng],   phi[kp][0], phi[kp][1], phi[kp][2], phi[kp][3], vh4[0], vh4[1]);
                MMA_BF16(oacc[2*ng+1], phi[kp][0], phi[kp][1], phi[kp][2], phi[kp][3], vh4[2], vh4[3]);
                MMA_BF16(oacc[2*ng],   plo[kp][0], plo[kp][1], plo[kp][2], plo[kp][3], vh4[0], vh4[1]);
                MMA_BF16(oacc[2*ng+1], plo[kp][0], plo[kp][1], plo[kp][2], plo[kp][3], vh4[2], vh4[3]);
                MMA_BF16(oacc[2*ng],   phi[kp][0], phi[kp][1], phi[kp][2], phi[kp][3], vl4[0], vl4[1]);
                MMA_BF16(oacc[2*ng+1], phi[kp][0], phi[kp][1], phi[kp][2], phi[kp][3], vl4[2], vl4[3]);
            }
        }
        __syncthreads();
        s ^= 1;
    }

    float il0 = 1.0f / lsum[0];
    float il1 = 1.0f / lsum[1];
    const int row0 = qrow0 + trow;
#pragma unroll
    for (int nf = 0; nf < 16; nf++) {
        int col = h * HD + nf * 8 + tc2;
        uint32_t hh, ll;
        split2(oacc[nf][0] * il0, oacc[nf][1] * il0, hh, ll);
        *(uint32_t*)&Yh[(size_t)row0 * C_DIM + col] = hh;
        *(uint32_t*)&Yl[(size_t)row0 * C_DIM + col] = ll;
        split2(oacc[nf][2] * il1, oacc[nf][3] * il1, hh, ll);
        *(uint32_t*)&Yh[(size_t)(row0 + 8) * C_DIM + col] = hh;
        *(uint32_t*)&Yl[(size_t)(row0 + 8) * C_DIM + col] = ll;
    }
}

// ---------------------------------------------------------------------------
// Launch (round-9 structure; position #4 = Wq GEMM for ncu capture)
// ---------------------------------------------------------------------------
extern "C" void kernel_launch(void* const* d_in, const int* in_sizes, int n_in,
                              void* d_out, int out_size)
{
    const float* x  = (const float*)d_in[0];
    const float* Wq = (const float*)d_in[1];
    const float* Wk = (const float*)d_in[2];
    const float* Wv = (const float*)d_in[3];
    const float* Wo = (const float*)d_in[4];
    float* out = (float*)d_out;

    float *Q, *Kp;
    cudaGetSymbolAddress((void**)&Q,  g_Q);
    cudaGetSymbolAddress((void**)&Kp, g_K);

    __nv_bfloat16 *xh, *xl, *yh, *yl, *wqh, *wql, *woh, *wol;
    cudaGetSymbolAddress((void**)&xh, g_xh);
    cudaGetSymbolAddress((void**)&xl, g_xl);
    cudaGetSymbolAddress((void**)&yh, g_yh);
    cudaGetSymbolAddress((void**)&yl, g_yl);
    cudaGetSymbolAddress((void**)&wqh, g_wqt_h);
    cudaGetSymbolAddress((void**)&wql, g_wqt_l);
    cudaGetSymbolAddress((void**)&woh, g_wot_h);
    cudaGetSymbolAddress((void**)&wol, g_wot_l);

    static bool attr_done = false;
    if (!attr_done) {
        cudaFuncSetAttribute(gemm_one, cudaFuncAttributeMaxDynamicSharedMemorySize, G2_SMEM);
        cudaFuncSetAttribute(gemm_kv,  cudaFuncAttributeMaxDynamicSharedMemorySize, G2_SMEM);
        cudaFuncSetAttribute(attn_tc_kernel, cudaFuncAttributeMaxDynamicSharedMemorySize, ATT_SMEM);
        attr_done = true;
    }

    // 1: RoPE table
    rope_table_kernel<<<(T_LEN * 64) / 256, 256>>>();
    // 2: split x
    split_f32_kernel<<<(T_LEN * C_DIM / 4 + 255) / 256, 256>>>(x, xh, xl, T_LEN * C_DIM / 4);
    // 3: transpose Wq + Wo
    transpose_qo_kernel<<<dim3(C_DIM / 32, C_DIM / 32, 2), dim3(32, 8)>>>(Wq, Wo);
    // 4: Q projection  <-- profiled launch
    gemm_one<<<dim3((HQ * HD) / 128, T_LEN / 256), 256, G2_SMEM>>>(xh, xl, wqh, wql, Q, T_LEN, HQ * HD, C_DIM);
    // 5: transpose Wk + Wv
    transpose_kv_kernel<<<dim3(NKV / 32, C_DIM / 32, 2), dim3(32, 8)>>>(Wk, Wv);
    // 6: K + V projections
    gemm_kv<<<dim3(NKV / 128, T_LEN / 256, 2), 256, G2_SMEM>>>(xh, xl, Kp);
    // 7: RoPE apply + split
    const int n_rope2 = T_LEN * HQ * 32 + T_LEN * HKV * 32;
    rope_apply_split_kernel<<<n_rope2 / 256, 256>>>(Q, Kp);
    // 8: attention (128q x 64k tiles)
    attn_tc_kernel<<<dim3(T_LEN / 128, HQ), 256, ATT_SMEM>>>(yh, yl);
    // 9: output projection
    gemm_one<<<dim3(C_DIM / 128, T_LEN / 256), 256, G2_SMEM>>>(yh, yl, woh, wol, out, T_LEN, C_DIM, C_DIM);
}

// round 13
// speedup vs baseline: 1.0521x; 1.0208x over previous
#include <cuda_runtime.h>
#include <cuda_bf16.h>
#include <math.h>
#include <float.h>
#include <stdint.h>

// Problem constants
#define T_LEN   4096
#define C_DIM   2048
#define HQ      16
#define HKV     4
#define HD      128
#define WIN     1024
#define NKV     (HKV * HD)     // 512

// fp32 scratch
__device__ float g_Q[T_LEN * HQ * HD];
__device__ float g_K[T_LEN * NKV];
__device__ float g_cos[T_LEN * 64];
__device__ float g_sin[T_LEN * 64];

// bf16 split operands
__device__ __nv_bfloat16 g_xh[T_LEN * C_DIM],  g_xl[T_LEN * C_DIM];
__device__ __nv_bfloat16 g_yh[T_LEN * C_DIM],  g_yl[T_LEN * C_DIM];
__device__ __nv_bfloat16 g_qsh[T_LEN * C_DIM], g_qsl[T_LEN * C_DIM];
__device__ __nv_bfloat16 g_ksh[T_LEN * NKV],   g_ksl[T_LEN * NKV];
__device__ __nv_bfloat16 g_vsh[T_LEN * NKV],   g_vsl[T_LEN * NKV];
__device__ __nv_bfloat16 g_wqt_h[C_DIM * C_DIM], g_wqt_l[C_DIM * C_DIM];
__device__ __nv_bfloat16 g_wkt_h[NKV * C_DIM],   g_wkt_l[NKV * C_DIM];
__device__ __nv_bfloat16 g_wvt_h[NKV * C_DIM],   g_wvt_l[NKV * C_DIM];
__device__ __nv_bfloat16 g_wot_h[C_DIM * C_DIM], g_wot_l[C_DIM * C_DIM];

// ---------------------------------------------------------------------------
// helpers
// ---------------------------------------------------------------------------
__device__ __forceinline__ uint32_t smem_u32(const void* p) {
    return (uint32_t)__cvta_generic_to_shared(p);
}

__device__ __forceinline__ void split2(float a, float b, uint32_t& hi, uint32_t& lo) {
    __nv_bfloat16 ah = __float2bfloat16_rn(a);
    __nv_bfloat16 bh = __float2bfloat16_rn(b);
    __nv_bfloat162 h(ah, bh);
    hi = *(uint32_t*)&h;
    __nv_bfloat162 l(__float2bfloat16_rn(a - __bfloat162float(ah)),
                     __float2bfloat16_rn(b - __bfloat162float(bh)));
    lo = *(uint32_t*)&l;
}

#define LDMATRIX_X4(R0,R1,R2,R3,ADDR) \
    asm volatile("ldmatrix.sync.aligned.m8n8.x4.shared.b16 {%0,%1,%2,%3}, [%4];" \
        : "=r"(R0), "=r"(R1), "=r"(R2), "=r"(R3) : "r"(ADDR))

#define LDMATRIX_X4_T(R0,R1,R2,R3,ADDR) \
    asm volatile("ldmatrix.sync.aligned.m8n8.x4.trans.shared.b16 {%0,%1,%2,%3}, [%4];" \
        : "=r"(R0), "=r"(R1), "=r"(R2), "=r"(R3) : "r"(ADDR))

#define MMA_BF16(D, A0,A1,A2,A3, B0,B1) \
    asm volatile("mma.sync.aligned.m16n8k16.row.col.f32.bf16.bf16.f32 " \
        "{%0,%1,%2,%3}, {%4,%5,%6,%7}, {%8,%9}, {%0,%1,%2,%3};" \
        : "+f"((D)[0]), "+f"((D)[1]), "+f"((D)[2]), "+f"((D)[3]) \
        : "r"(A0), "r"(A1), "r"(A2), "r"(A3), "r"(B0), "r"(B1))

__device__ __forceinline__ void cp_async16(uint32_t dst, const void* src) {
    asm volatile("cp.async.cg.shared.global [%0], [%1], 16;" :: "r"(dst), "l"(src));
}
__device__ __forceinline__ void cp_commit() {
    asm volatile("cp.async.commit_group;" ::: "memory");
}
template <int NN> __device__ __forceinline__ void cp_wait() {
    asm volatile("cp.async.wait_group %0;" :: "n"(NN) : "memory");
}

// ---------------------------------------------------------------------------
// Prep kernels
// ---------------------------------------------------------------------------
__global__ void split_f32_kernel(const float* __restrict__ src,
                                 __nv_bfloat16* __restrict__ hi,
                                 __nv_bfloat16* __restrict__ lo, int n4)
{
    int i = blockIdx.x * blockDim.x + threadIdx.x;
    if (i >= n4) return;
    float4 v = ((const float4*)src)[i];
    uint32_t h0, l0, h1, l1;
    split2(v.x, v.y, h0, l0);
    split2(v.z, v.w, h1, l1);
    ((uint2*)hi)[i] = make_uint2(h0, h1);
    ((uint2*)lo)[i] = make_uint2(l0, l1);
}

__device__ __forceinline__ void transpose_split_body(
    const float* __restrict__ W, __nv_bfloat16* __restrict__ Th,
    __nv_bfloat16* __restrict__ Tl, int Kd, int Nd)
{
    __shared__ float tile[32][33];
    const int bx = blockIdx.x;
    const int by = blockIdx.y;
    const int x = threadIdx.x;
    const int y = threadIdx.y;
#pragma unroll
    for (int j = 0; j < 32; j += 8)
        tile[y + j][x] = W[(size_t)(by * 32 + y + j) * Nd + bx * 32 + x];
    __syncthreads();
#pragma unroll
    for (int j = 0; j < 32; j += 8) {
        float v = tile[x][y + j];
        __nv_bfloat16 h = __float2bfloat16_rn(v);
        size_t o = (size_t)(bx * 32 + y + j) * Kd + by * 32 + x;
        Th[o] = h;
        Tl[o] = __float2bfloat16_rn(v - __bfloat162float(h));
    }
}

__global__ void transpose_qo_kernel(const float* __restrict__ Wq, const float* __restrict__ Wo)
{
    if (blockIdx.z == 0) transpose_split_body(Wq, g_wqt_h, g_wqt_l, C_DIM, C_DIM);
    else                 transpose_split_body(Wo, g_wot_h, g_wot_l, C_DIM, C_DIM);
}

__global__ void transpose_kv_kernel(const float* __restrict__ Wk, const float* __restrict__ Wv)
{
    if (blockIdx.z == 0) transpose_split_body(Wk, g_wkt_h, g_wkt_l, C_DIM, NKV);
    else                 transpose_split_body(Wv, g_wvt_h, g_wvt_l, C_DIM, NKV);
}

// ---------------------------------------------------------------------------
// bf16x3 GEMM: C[M,N] = A[M,K] * B[N,K]^T, pre-split bf16 operands.
// 256x128 block tile, BK=64, 256 threads (8 warps, 64x64 warp tiles),
// 2-stage cp.async pipeline, ONE barrier per iteration.
// ---------------------------------------------------------------------------
#define G2_AH 0
#define G2_AL 32768
#define G2_BH 65536
#define G2_BL 81920
#define G2_STAGE 98304
#define G2_SMEM  (2 * G2_STAGE)   // 196608

__device__ __forceinline__ void g_load_stage(uint32_t dstbase,
    const __nv_bfloat16* __restrict__ Ah, const __nv_bfloat16* __restrict__ Al,
    const __nv_bfloat16* __restrict__ Bh, const __nv_bfloat16* __restrict__ Bl,
    int bm, int bn, int k0, int K, int tid)
{
    const int row = tid >> 3;
    const int c   = tid & 7;
    const uint32_t swc = (uint32_t)((c ^ (row & 7)) << 4);
#pragma unroll
    for (int jj = 0; jj < 8; jj++) {
        int r = row + 32 * jj;
        uint32_t so = (uint32_t)r * 128 + swc;
        size_t ga = (size_t)(bm + r) * K + k0 + c * 8;
        cp_async16(dstbase + G2_AH + so, Ah + ga);
        cp_async16(dstbase + G2_AL + so, Al + ga);
    }
#pragma unroll
    for (int jj = 0; jj < 4; jj++) {
        int r = row + 32 * jj;
        uint32_t so = (uint32_t)r * 128 + swc;
        size_t gb = (size_t)(bn + r) * K + k0 + c * 8;
        cp_async16(dstbase + G2_BH + so, Bh + gb);
        cp_async16(dstbase + G2_BL + so, Bl + gb);
    }
}

__device__ void gemm_body(
    const __nv_bfloat16* __restrict__ Ah, const __nv_bfloat16* __restrict__ Al,
    const __nv_bfloat16* __restrict__ Bh, const __nv_bfloat16* __restrict__ Bl,
    float* __restrict__ C, __nv_bfloat16* __restrict__ Ch, __nv_bfloat16* __restrict__ Cl,
    int splitout, int M, int N, int K, int bxx, int byy)
{
    extern __shared__ char smg[];
    const int tid  = threadIdx.x;
    const int wid  = tid >> 5;
    const int lane = tid & 31;
    const int warp_m = wid & 3;
    const int warp_n = wid >> 2;
    const int bm = byy * 256;
    const int bn = bxx * 128;
    const uint32_t sbase = smem_u32(smg);

    const int ar  = (lane & 7) | (((lane >> 3) & 1) << 3);
    const int ag  = lane >> 4;
    const int ar7 = ar & 7;
    const int br  = (lane & 7) | ((lane >> 4) << 3);
    const int bg  = (lane >> 3) & 1;
    const int br7 = lane & 7;

    uint32_t a_ro[4], b_ro[4];
#pragma unroll
    for (int mi = 0; mi < 4; mi++)
        a_ro[mi] = (uint32_t)(warp_m * 64 + mi * 16 + ar) * 128 + G2_AH;
#pragma unroll
    for (int ng = 0; ng < 4; ng++)
        b_ro[ng] = (uint32_t)(warp_n * 64 + ng * 16 + br) * 128 + G2_BH;

    float acc[4][8][4];
#pragma unroll
    for (int mi = 0; mi < 4; mi++)
#pragma unroll
        for (int nf = 0; nf < 8; nf++)
#pragma unroll
            for (int e = 0; e < 4; e++) acc[mi][nf][e] = 0.0f;

    const int NK = K >> 6;

    g_load_stage(sbase, Ah, Al, Bh, Bl, bm, bn, 0, K, tid);
    cp_commit();

    for (int i = 0; i < NK; i++) {
        cp_wait<0>();          // this thread's load(i) complete
        __syncthreads();       // data visible; all warps done compute(i-1)

        if (i + 1 < NK) {
            g_load_stage(sbase + ((i + 1) & 1) * G2_STAGE, Ah, Al, Bh, Bl,
                         bm, bn, (i + 1) * 64, K, tid);
            cp_commit();
        }

        const uint32_t stb = sbase + (i & 1) * G2_STAGE;
#pragma unroll
        for (int ks = 0; ks < 4; ks++) {
            const uint32_t cA = (uint32_t)(((ks * 2 + ag) ^ ar7) << 4);
            const uint32_t cB = (uint32_t)(((ks * 2 + bg) ^ br7) << 4);
            uint32_t ahi[4][4], alo[4][4];
#pragma unroll
            for (int mi = 0; mi < 4; mi++) {
                uint32_t ad = stb + a_ro[mi] + cA;
                LDMATRIX_X4(ahi[mi][0], ahi[mi][1], ahi[mi][2], ahi[mi][3], ad);
                LDMATRIX_X4(alo[mi][0], alo[mi][1], alo[mi][2], alo[mi][3], ad + 32768);
            }
            uint32_t bhi[4][4], blo[4][4];
#pragma unroll
            for (int ng = 0; ng < 4; ng++) {
                uint32_t bd = stb + b_ro[ng] + cB;
                LDMATRIX_X4(bhi[ng][0], bhi[ng][1], bhi[ng][2], bhi[ng][3], bd);
                LDMATRIX_X4(blo[ng][0], blo[ng][1], blo[ng][2], blo[ng][3], bd + 16384);
            }
#pragma unroll
            for (int mi = 0; mi < 4; mi++)
#pragma unroll
                for (int ng = 0; ng < 4; ng++) {
                    MMA_BF16(acc[mi][2*ng],   ahi[mi][0], ahi[mi][1], ahi[mi][2], ahi[mi][3], bhi[ng][0], bhi[ng][1]);
                    MMA_BF16(acc[mi][2*ng+1], ahi[mi][0], ahi[mi][1], ahi[mi][2], ahi[mi][3], bhi[ng][2], bhi[ng][3]);
                }
#pragma unroll
            for (int mi = 0; mi < 4; mi++)
#pragma unroll
                for (int ng = 0; ng < 4; ng++) {
                    MMA_BF16(acc[mi][2*ng],   ahi[mi][0], ahi[mi][1], ahi[mi][2], ahi[mi][3], blo[ng][0], blo[ng][1]);
                    MMA_BF16(acc[mi][2*ng+1], ahi[mi][0], ahi[mi][1], ahi[mi][2], ahi[mi][3], blo[ng][2], blo[ng][3]);
                }
#pragma unroll
            for (int mi = 0; mi < 4; mi++)
#pragma unroll
                for (int ng = 0; ng < 4; ng++) {
                    MMA_BF16(acc[mi][2*ng],   alo[mi][0], alo[mi][1], alo[mi][2], alo[mi][3], bhi[ng][0], bhi[ng][1]);
                    MMA_BF16(acc[mi][2*ng+1], alo[mi][0], alo[mi][1], alo[mi][2], alo[mi][3], bhi[ng][2], bhi[ng][3]);
                }
        }
        // no trailing barrier: next iteration's post-wait barrier protects
        // the stage being overwritten (loads are issued only after it).
    }

    const int trow = lane >> 2;
    const int tcol = (lane & 3) << 1;
#pragma unroll
    for (int mi = 0; mi < 4; mi++) {
#pragma unroll
        for (int nf = 0; nf < 8; nf++) {
            int rg = bm + warp_m * 64 + mi * 16 + trow;
            int cg = bn + warp_n * 64 + nf * 8 + tcol;
            if (!splitout) {
                *(float2*)&C[(size_t)rg * N + cg]       = make_float2(acc[mi][nf][0], acc[mi][nf][1]);
                *(float2*)&C[(size_t)(rg + 8) * N + cg] = make_float2(acc[mi][nf][2], acc[mi][nf][3]);
            } else {
                uint32_t hh, ll;
                split2(acc[mi][nf][0], acc[mi][nf][1], hh, ll);
                *(uint32_t*)&Ch[(size_t)rg * N + cg] = hh;
                *(uint32_t*)&Cl[(size_t)rg * N + cg] = ll;
                split2(acc[mi][nf][2], acc[mi][nf][3], hh, ll);
                *(uint32_t*)&Ch[(size_t)(rg + 8) * N + cg] = hh;
                *(uint32_t*)&Cl[(size_t)(rg + 8) * N + cg] = ll;
            }
        }
    }
}

__global__ __launch_bounds__(256)
void gemm_one(const __nv_bfloat16* Ah, const __nv_bfloat16* Al,
              const __nv_bfloat16* Bh, const __nv_bfloat16* Bl,
              float* C, int M, int N, int K)
{
    gemm_body(Ah, Al, Bh, Bl, C, nullptr, nullptr, 0, M, N, K, blockIdx.x, blockIdx.y);
}

__global__ __launch_bounds__(256)
void gemm_kv(const __nv_bfloat16* Ah, const __nv_bfloat16* Al, float* Kout)
{
    if (blockIdx.z == 0)
        gemm_body(Ah, Al, g_wkt_h, g_wkt_l, Kout, nullptr, nullptr, 0,
                  T_LEN, NKV, C_DIM, blockIdx.x, blockIdx.y);
    else
        gemm_body(Ah, Al, g_wvt_h, g_wvt_l, nullptr, g_vsh, g_vsl, 1,
                  T_LEN, NKV, C_DIM, blockIdx.x, blockIdx.y);
}

// ---------------------------------------------------------------------------
// RoPE
// ---------------------------------------------------------------------------
__global__ void rope_table_kernel()
{
    __shared__ float s_invf[64];
    if (threadIdx.x < 64) {
        double e = exp(-(double)threadIdx.x * (log(10000.0) / 64.0));
        s_invf[threadIdx.x] = (float)e;
    }
    __syncthreads();
    int idx = blockIdx.x * blockDim.x + threadIdx.x;
    if (idx >= T_LEN * 64) return;
    int t = idx >> 6;
    int j = idx & 63;
    float ang = (float)t * s_invf[j];
    float s, c;
    sincosf(ang, &s, &c);
    g_cos[idx] = c;
    g_sin[idx] = s;
}

__global__ void rope_apply_split_kernel(const float* __restrict__ Q,
                                        const float* __restrict__ K)
{
    const float SCQ = (float)(0.08838834764831845 * 1.4426950408889634);
    const int NQ2 = T_LEN * HQ * 32;
    int idx = blockIdx.x * blockDim.x + threadIdx.x;
    if (idx < NQ2) {
        int t = idx >> 9;
        int rem = idx & 511;
        int h = rem >> 5;
        int j2 = (rem & 31) << 1;
        size_t o = (size_t)t * C_DIM + h * HD;
        const float* p = Q + o;
        float2 x0 = *(const float2*)(p + j2);
        float2 x1 = *(const float2*)(p + j2 + 64);
        float2 cv = *(const float2*)(g_cos + t * 64 + j2);
        float2 sv = *(const float2*)(g_sin + t * 64 + j2);
        float r0a = (x0.x * cv.x - x1.x * sv.x) * SCQ;
        float r0b = (x0.y * cv.y - x1.y * sv.y) * SCQ;
        float r1a = (x1.x * cv.x + x0.x * sv.x) * SCQ;
        float r1b = (x1.y * cv.y + x0.y * sv.y) * SCQ;
        uint32_t hh, ll;
        split2(r0a, r0b, hh, ll);
        *(uint32_t*)&g_qsh[o + j2] = hh;
        *(uint32_t*)&g_qsl[o + j2] = ll;
        split2(r1a, r1b, hh, ll);
        *(uint32_t*)&g_qsh[o + j2 + 64] = hh;
        *(uint32_t*)&g_qsl[o + j2 + 64] = ll;
    } else {
        int i2 = idx - NQ2;
        int t = i2 >> 7;
        int rem = i2 & 127;
        int h = rem >> 5;
        int j2 = (rem & 31) << 1;
        size_t o = (size_t)t * NKV + h * HD;
        const float* p = K + o;
        float2 x0 = *(const float2*)(p + j2);
        float2 x1 = *(const float2*)(p + j2 + 64);
        float2 cv = *(const float2*)(g_cos + t * 64 + j2);
        float2 sv = *(const float2*)(g_sin + t * 64 + j2);
        float r0a = x0.x * cv.x - x1.x * sv.x;
        float r0b = x0.y * cv.y - x1.y * sv.y;
        float r1a = x1.x * cv.x + x0.x * sv.x;
        float r1b = x1.y * cv.y + x0.y * sv.y;
        uint32_t hh, ll;
        split2(r0a, r0b, hh, ll);
        *(uint32_t*)&g_ksh[o + j2] = hh;
        *(uint32_t*)&g_ksl[o + j2] = ll;
        split2(r1a, r1b, hh, ll);
        *(uint32_t*)&g_ksh[o + j2 + 64] = hh;
        *(uint32_t*)&g_ksl[o + j2 + 64] = ll;
    }
}

// ---------------------------------------------------------------------------
// Flash attention, GQA-packed: each block = 32 queries x 4 Q-heads (one KV
// head) = 128 MMA rows, 64-key tiles, 256 threads. Warp w owns head
// kvh*4 + (w>>1), query rows q0 + (w&1)*16 + trow{,+8}. KV loaded once per
// 4 heads; narrower q-span widens the mask-free window.
// ---------------------------------------------------------------------------
#define KVS   136
#define AR_SZ (64 * KVS * 2)
#define A_KH  0
#define A_KL  AR_SZ
#define A_VH  (2 * AR_SZ)
#define A_VL  (3 * AR_SZ)
#define ATT_STAGE (4 * AR_SZ)
#define ATT_SMEM  (2 * ATT_STAGE)

__device__ __forceinline__ void attn_load_kv(uint32_t dstbase, int jb, int kvh, int tid)
{
#pragma unroll
    for (int i = 0; i < 4; i++) {
        int idx = tid + 256 * i;
        int row = idx >> 4;
        int c16 = idx & 15;
        uint32_t so = (uint32_t)row * (KVS * 2) + c16 * 16;
        size_t g = (size_t)(jb + row) * NKV + kvh * HD + c16 * 8;
        cp_async16(dstbase + A_KH + so, g_ksh + g);
        cp_async16(dstbase + A_KL + so, g_ksl + g);
        cp_async16(dstbase + A_VH + so, g_vsh + g);
        cp_async16(dstbase + A_VL + so, g_vsl + g);
    }
}

__global__ __launch_bounds__(256)
void attn_tc_kernel(__nv_bfloat16* __restrict__ Yh, __nv_bfloat16* __restrict__ Yl)
{
    extern __shared__ char sma[];
    const uint32_t sbase = smem_u32(sma);

    const int qb  = blockIdx.x;            // 32-query block
    const int kvh = blockIdx.y;            // KV head
    const int tid  = threadIdx.x;
    const int wid  = tid >> 5;
    const int lane = tid & 31;
    const int trow = lane >> 2;
    const int tc2  = (lane & 3) << 1;

    const int q0    = qb * 32;
    const int head  = kvh * 4 + (wid >> 1);          // Q head for this warp
    const int qbase = q0 + ((wid & 1) << 4);         // this warp's 16-query slice

    // Q fragments (pre-scaled, pre-split)
    uint32_t qhi[8][4], qlo[8][4];
#pragma unroll
    for (int ks = 0; ks < 8; ks++) {
#pragma unroll
        for (int r = 0; r < 4; r++) {
            int row = qbase + trow + ((r & 1) << 3);
            int d = ks * 16 + ((r >> 1) << 3) + tc2;
            size_t o = (size_t)row * C_DIM + head * HD + d;
            qhi[ks][r] = *(const uint32_t*)&g_qsh[o];
            qlo[ks][r] = *(const uint32_t*)&g_qsl[o];
        }
    }

    float oacc[16][4];
#pragma unroll
    for (int nf = 0; nf < 16; nf++)
#pragma unroll
        for (int e = 0; e < 4; e++) oacc[nf][e] = 0.0f;
    float m2[2]   = { -1e30f, -1e30f };
    float lsum[2] = { 0.0f, 0.0f };

    int jmin = q0 - (WIN - 1);
    if (jmin < 0) jmin = 0;
    const int kb0 = jmin >> 6;
    const int kb1 = (q0 + 31) >> 6;

    const int krow    = (lane & 7) + ((lane >> 4) << 3);
    const int kcoloff = ((lane >> 3) & 1) << 3;
    const int vrow    = (lane & 7) + (((lane >> 3) & 1) << 3);
    const int vcoloff = (lane >> 4) << 3;

    const uint32_t kh_ro = (uint32_t)(krow * KVS + kcoloff) * 2;
    const uint32_t vh_ro = (uint32_t)(vrow * KVS + vcoloff) * 2;
    const uint32_t KROW16 = (uint32_t)(16 * KVS) * 2;

    attn_load_kv(sbase, kb0 * 64, kvh, tid);
    cp_commit();

    int s = 0;
    for (int kb = kb0; kb <= kb1; kb++) {
        const int jb = kb * 64;
        if (kb < kb1) {
            attn_load_kv(sbase + (s ^ 1) * ATT_STAGE, (kb + 1) * 64, kvh, tid);
            cp_commit();
            cp_wait<1>();
        } else {
            cp_wait<0>();
        }
        __syncthreads();

        const uint32_t stb = sbase + s * ATT_STAGE;
        const uint32_t kh_base = stb + A_KH + kh_ro;
        const uint32_t vh_base = stb + A_VH + vh_ro;
        const uint32_t vl_base = stb + A_VL + vh_ro;

        float sacc[8][4];
#pragma unroll
        for (int f = 0; f < 8; f++)
#pragma unroll
            for (int e = 0; e < 4; e++) sacc[f][e] = 0.0f;

#pragma unroll
        for (int ks = 0; ks < 8; ks++) {
            uint32_t off = (uint32_t)(ks * 16) * 2;
#pragma unroll
            for (int g = 0; g < 4; g++) {
                uint32_t bh[4], bl[4];
                uint32_t ad = kh_base + off + g * KROW16;
                LDMATRIX_X4(bh[0], bh[1], bh[2], bh[3], ad);
                LDMATRIX_X4(bl[0], bl[1], bl[2], bl[3], ad + AR_SZ);
                const int f0 = 2 * g, f1 = 2 * g + 1;
                MMA_BF16(sacc[f0], qhi[ks][0], qhi[ks][1], qhi[ks][2], qhi[ks][3], bh[0], bh[1]);
                MMA_BF16(sacc[f1], qhi[ks][0], qhi[ks][1], qhi[ks][2], qhi[ks][3], bh[2], bh[3]);
                MMA_BF16(sacc[f0], qlo[ks][0], qlo[ks][1], qlo[ks][2], qlo[ks][3], bh[0], bh[1]);
                MMA_BF16(sacc[f1], qlo[ks][0], qlo[ks][1], qlo[ks][2], qlo[ks][3], bh[2], bh[3]);
                MMA_BF16(sacc[f0], qhi[ks][0], qhi[ks][1], qhi[ks][2], qhi[ks][3], bl[0], bl[1]);
                MMA_BF16(sacc[f1], qhi[ks][0], qhi[ks][1], qhi[ks][2], qhi[ks][3], bl[2], bl[3]);
            }
        }

        // mask (hoisted): full tile iff all (q in [q0, q0+31], j in tile) valid
        const bool full = (jb + 64 <= q0) && (jb >= q0 - (WIN - 32));
        if (!full) {
#pragma unroll
            for (int f = 0; f < 8; f++) {
                int j0 = jb + f * 8 + tc2;
#pragma unroll
                for (int e = 0; e < 4; e++) {
                    int j  = j0 + (e & 1);
                    int qi = qbase + trow + ((e >> 1) << 3);
                    bool ok = (j <= qi) && ((qi - j) < WIN);
                    if (!ok) sacc[f][e] = -1e30f;
                }
            }
        }

        float bm0 = -1e30f, bm1 = -1e30f;
#pragma unroll
        for (int f = 0; f < 8; f++) {
            bm0 = fmaxf(bm0, fmaxf(sacc[f][0], sacc[f][1]));
            bm1 = fmaxf(bm1, fmaxf(sacc[f][2], sacc[f][3]));
        }
        bm0 = fmaxf(bm0, __shfl_xor_sync(0xffffffffu, bm0, 1));
        bm0 = fmaxf(bm0, __shfl_xor_sync(0xffffffffu, bm0, 2));
        bm1 = fmaxf(bm1, __shfl_xor_sync(0xffffffffu, bm1, 1));
        bm1 = fmaxf(bm1, __shfl_xor_sync(0xffffffffu, bm1, 2));

        float mn0 = fmaxf(m2[0], bm0);
        float mn1 = fmaxf(m2[1], bm1);
        float mm0 = fmaxf(mn0, -1e20f);
        float mm1 = fmaxf(mn1, -1e20f);
        float f0 = exp2f(m2[0] - mm0);
        float f1 = exp2f(m2[1] - mm1);
        m2[0] = mn0; m2[1] = mn1;

        float ps0 = 0.0f, ps1 = 0.0f;
#pragma unroll
        for (int f = 0; f < 8; f++) {
            sacc[f][0] = exp2f(sacc[f][0] - mm0);
            sacc[f][1] = exp2f(sacc[f][1] - mm0);
            sacc[f][2] = exp2f(sacc[f][2] - mm1);
            sacc[f][3] = exp2f(sacc[f][3] - mm1);
            ps0 += sacc[f][0] + sacc[f][1];
            ps1 += sacc[f][2] + sacc[f][3];
        }
        ps0 += __shfl_xor_sync(0xffffffffu, ps0, 1);
        ps0 += __shfl_xor_sync(0xffffffffu, ps0, 2);
        ps1 += __shfl_xor_sync(0xffffffffu, ps1, 1);
        ps1 += __shfl_xor_sync(0xffffffffu, ps1, 2);
        lsum[0] = lsum[0] * f0 + ps0;
        lsum[1] = lsum[1] * f1 + ps1;

#pragma unroll
        for (int nf = 0; nf < 16; nf++) {
            oacc[nf][0] *= f0; oacc[nf][1] *= f0;
            oacc[nf][2] *= f1; oacc[nf][3] *= f1;
        }

        uint32_t phi[4][4], plo[4][4];
#pragma unroll
        for (int kp = 0; kp < 4; kp++) {
            split2(sacc[2*kp][0],   sacc[2*kp][1],   phi[kp][0], plo[kp][0]);
            split2(sacc[2*kp][2],   sacc[2*kp][3],   phi[kp][1], plo[kp][1]);
            split2(sacc[2*kp+1][0], sacc[2*kp+1][1], phi[kp][2], plo[kp][2]);
            split2(sacc[2*kp+1][2], sacc[2*kp+1][3], phi[kp][3], plo[kp][3]);
        }

#pragma unroll
        for (int kp = 0; kp < 4; kp++) {
            uint32_t rowoff = (uint32_t)(kp * 16 * KVS) * 2;
#pragma unroll
            for (int ng = 0; ng < 8; ng++) {
                uint32_t coff = rowoff + (uint32_t)(ng * 16) * 2;
                uint32_t vh4[4], vl4[4];
                LDMATRIX_X4_T(vh4[0], vh4[1], vh4[2], vh4[3], vh_base + coff);
                LDMATRIX_X4_T(vl4[0], vl4[1], vl4[2], vl4[3], vl_base + coff);
                MMA_BF16(oacc[2*ng],   phi[kp][0], phi[kp][1], phi[kp][2], phi[kp][3], vh4[0], vh4[1]);
                MMA_BF16(oacc[2*ng+1], phi[kp][0], phi[kp][1], phi[kp][2], phi[kp][3], vh4[2], vh4[3]);
                MMA_BF16(oacc[2*ng],   plo[kp][0], plo[kp][1], plo[kp][2], plo[kp][3], vh4[0], vh4[1]);
                MMA_BF16(oacc[2*ng+1], plo[kp][0], plo[kp][1], plo[kp][2], plo[kp][3], vh4[2], vh4[3]);
                MMA_BF16(oacc[2*ng],   phi[kp][0], phi[kp][1], phi[kp][2], phi[kp][3], vl4[0], vl4[1]);
                MMA_BF16(oacc[2*ng+1], phi[kp][0], phi[kp][1], phi[kp][2], phi[kp][3], vl4[2], vl4[3]);
            }
        }
        __syncthreads();
        s ^= 1;
    }

    float il0 = 1.0f / lsum[0];
    float il1 = 1.0f / lsum[1];
    const int row0 = qbase + trow;
#pragma unroll
    for (int nf = 0; nf < 16; nf++) {
        int col = head * HD + nf * 8 + tc2;
        uint32_t hh, ll;
        split2(oacc[nf][0] * il0, oacc[nf][1] * il0, hh, ll);
        *(uint32_t*)&Yh[(size_t)row0 * C_DIM + col] = hh;
        *(uint32_t*)&Yl[(size_t)row0 * C_DIM + col] = ll;
        split2(oacc[nf][2] * il1, oacc[nf][3] * il1, hh, ll);
        *(uint32_t*)&Yh[(size_t)(row0 + 8) * C_DIM + col] = hh;
        *(uint32_t*)&Yl[(size_t)(row0 + 8) * C_DIM + col] = ll;
    }
}

// ---------------------------------------------------------------------------
// Launch (position #4 = Wq GEMM for ncu capture)
// ---------------------------------------------------------------------------
extern "C" void kernel_launch(void* const* d_in, const int* in_sizes, int n_in,
                              void* d_out, int out_size)
{
    const float* x  = (const float*)d_in[0];
    const float* Wq = (const float*)d_in[1];
    const float* Wk = (const float*)d_in[2];
    const float* Wv = (const float*)d_in[3];
    const float* Wo = (const float*)d_in[4];
    float* out = (float*)d_out;

    float *Q, *Kp;
    cudaGetSymbolAddress((void**)&Q,  g_Q);
    cudaGetSymbolAddress((void**)&Kp, g_K);

    __nv_bfloat16 *xh, *xl, *yh, *yl, *wqh, *wql, *woh, *wol;
    cudaGetSymbolAddress((void**)&xh, g_xh);
    cudaGetSymbolAddress((void**)&xl, g_xl);
    cudaGetSymbolAddress((void**)&yh, g_yh);
    cudaGetSymbolAddress((void**)&yl, g_yl);
    cudaGetSymbolAddress((void**)&wqh, g_wqt_h);
    cudaGetSymbolAddress((void**)&wql, g_wqt_l);
    cudaGetSymbolAddress((void**)&woh, g_wot_h);
    cudaGetSymbolAddress((void**)&wol, g_wot_l);

    static bool attr_done = false;
    if (!attr_done) {
        cudaFuncSetAttribute(gemm_one, cudaFuncAttributeMaxDynamicSharedMemorySize, G2_SMEM);
        cudaFuncSetAttribute(gemm_kv,  cudaFuncAttributeMaxDynamicSharedMemorySize, G2_SMEM);
        cudaFuncSetAttribute(attn_tc_kernel, cudaFuncAttributeMaxDynamicSharedMemorySize, ATT_SMEM);
        attr_done = true;
    }

    // 1: RoPE table
    rope_table_kernel<<<(T_LEN * 64) / 256, 256>>>();
    // 2: split x
    split_f32_kernel<<<(T_LEN * C_DIM / 4 + 255) / 256, 256>>>(x, xh, xl, T_LEN * C_DIM / 4);
    // 3: transpose Wq + Wo
    transpose_qo_kernel<<<dim3(C_DIM / 32, C_DIM / 32, 2), dim3(32, 8)>>>(Wq, Wo);
    // 4: Q projection  <-- profiled launch
    gemm_one<<<dim3((HQ * HD) / 128, T_LEN / 256), 256, G2_SMEM>>>(xh, xl, wqh, wql, Q, T_LEN, HQ * HD, C_DIM);
    // 5: transpose Wk + Wv
    transpose_kv_kernel<<<dim3(NKV / 32, C_DIM / 32, 2), dim3(32, 8)>>>(Wk, Wv);
    // 6: K + V projections
    gemm_kv<<<dim3(NKV / 128, T_LEN / 256, 2), 256, G2_SMEM>>>(xh, xl, Kp);
    // 7: RoPE apply + split
    const int n_rope2 = T_LEN * HQ * 32 + T_LEN * HKV * 32;
    rope_apply_split_kernel<<<n_rope2 / 256, 256>>>(Q, Kp);
    // 8: attention (GQA-packed: 32q x 4 heads per block)
    attn_tc_kernel<<<dim3(T_LEN / 32, HKV), 256, ATT_SMEM>>>(yh, yl);
    // 9: output projection
    gemm_one<<<dim3(C_DIM / 128, T_LEN / 256), 256, G2_SMEM>>>(yh, yl, woh, wol, out, T_LEN, C_DIM, C_DIM);
}

// round 14
// speedup vs baseline: 1.0756x; 1.0223x over previous
#include <cuda_runtime.h>
#include <cuda_bf16.h>
#include <math.h>
#include <float.h>
#include <stdint.h>

// Problem constants
#define T_LEN   4096
#define C_DIM   2048
#define HQ      16
#define HKV     4
#define HD      128
#define WIN     1024
#define NKV     (HKV * HD)     // 512

#define SCQ_CONST 0.1275174541395871f  // 1/sqrt(128) * log2(e)

// fp32 scratch
__device__ float g_Q[T_LEN * HQ * HD];
__device__ float g_K[T_LEN * NKV];
__device__ float g_cos[T_LEN * 64];
__device__ float g_sin[T_LEN * 64];

// bf16 split operands
__device__ __nv_bfloat16 g_xh[T_LEN * C_DIM],  g_xl[T_LEN * C_DIM];
__device__ __nv_bfloat16 g_yh[T_LEN * C_DIM],  g_yl[T_LEN * C_DIM];
__device__ __nv_bfloat16 g_ksh[T_LEN * NKV],   g_ksl[T_LEN * NKV];
__device__ __nv_bfloat16 g_vsh[T_LEN * NKV],   g_vsl[T_LEN * NKV];
__device__ __nv_bfloat16 g_wqt_h[C_DIM * C_DIM], g_wqt_l[C_DIM * C_DIM];
__device__ __nv_bfloat16 g_wkt_h[NKV * C_DIM],   g_wkt_l[NKV * C_DIM];
__device__ __nv_bfloat16 g_wvt_h[NKV * C_DIM],   g_wvt_l[NKV * C_DIM];
__device__ __nv_bfloat16 g_wot_h[C_DIM * C_DIM], g_wot_l[C_DIM * C_DIM];

// ---------------------------------------------------------------------------
// helpers
// ---------------------------------------------------------------------------
__device__ __forceinline__ uint32_t smem_u32(const void* p) {
    return (uint32_t)__cvta_generic_to_shared(p);
}

__device__ __forceinline__ void split2(float a, float b, uint32_t& hi, uint32_t& lo) {
    __nv_bfloat16 ah = __float2bfloat16_rn(a);
    __nv_bfloat16 bh = __float2bfloat16_rn(b);
    __nv_bfloat162 h(ah, bh);
    hi = *(uint32_t*)&h;
    __nv_bfloat162 l(__float2bfloat16_rn(a - __bfloat162float(ah)),
                     __float2bfloat16_rn(b - __bfloat162float(bh)));
    lo = *(uint32_t*)&l;
}

#define LDMATRIX_X4(R0,R1,R2,R3,ADDR) \
    asm volatile("ldmatrix.sync.aligned.m8n8.x4.shared.b16 {%0,%1,%2,%3}, [%4];" \
        : "=r"(R0), "=r"(R1), "=r"(R2), "=r"(R3) : "r"(ADDR))

#define LDMATRIX_X4_T(R0,R1,R2,R3,ADDR) \
    asm volatile("ldmatrix.sync.aligned.m8n8.x4.trans.shared.b16 {%0,%1,%2,%3}, [%4];" \
        : "=r"(R0), "=r"(R1), "=r"(R2), "=r"(R3) : "r"(ADDR))

#define MMA_BF16(D, A0,A1,A2,A3, B0,B1) \
    asm volatile("mma.sync.aligned.m16n8k16.row.col.f32.bf16.bf16.f32 " \
        "{%0,%1,%2,%3}, {%4,%5,%6,%7}, {%8,%9}, {%0,%1,%2,%3};" \
        : "+f"((D)[0]), "+f"((D)[1]), "+f"((D)[2]), "+f"((D)[3]) \
        : "r"(A0), "r"(A1), "r"(A2), "r"(A3), "r"(B0), "r"(B1))

__device__ __forceinline__ void cp_async16(uint32_t dst, const void* src) {
    asm volatile("cp.async.cg.shared.global [%0], [%1], 16;" :: "r"(dst), "l"(src));
}
__device__ __forceinline__ void cp_commit() {
    asm volatile("cp.async.commit_group;" ::: "memory");
}
template <int NN> __device__ __forceinline__ void cp_wait() {
    asm volatile("cp.async.wait_group %0;" :: "n"(NN) : "memory");
}

// ---------------------------------------------------------------------------
// Prep kernels
// ---------------------------------------------------------------------------
__global__ void split_f32_kernel(const float* __restrict__ src,
                                 __nv_bfloat16* __restrict__ hi,
                                 __nv_bfloat16* __restrict__ lo, int n4)
{
    int i = blockIdx.x * blockDim.x + threadIdx.x;
    if (i >= n4) return;
    float4 v = ((const float4*)src)[i];
    uint32_t h0, l0, h1, l1;
    split2(v.x, v.y, h0, l0);
    split2(v.z, v.w, h1, l1);
    ((uint2*)hi)[i] = make_uint2(h0, h1);
    ((uint2*)lo)[i] = make_uint2(l0, l1);
}

__device__ __forceinline__ void transpose_split_body(
    const float* __restrict__ W, __nv_bfloat16* __restrict__ Th,
    __nv_bfloat16* __restrict__ Tl, int Kd, int Nd)
{
    __shared__ float tile[32][33];
    const int bx = blockIdx.x;
    const int by = blockIdx.y;
    const int x = threadIdx.x;
    const int y = threadIdx.y;
#pragma unroll
    for (int j = 0; j < 32; j += 8)
        tile[y + j][x] = W[(size_t)(by * 32 + y + j) * Nd + bx * 32 + x];
    __syncthreads();
#pragma unroll
    for (int j = 0; j < 32; j += 8) {
        float v = tile[x][y + j];
        __nv_bfloat16 h = __float2bfloat16_rn(v);
        size_t o = (size_t)(bx * 32 + y + j) * Kd + by * 32 + x;
        Th[o] = h;
        Tl[o] = __float2bfloat16_rn(v - __bfloat162float(h));
    }
}

__global__ void transpose_qo_kernel(const float* __restrict__ Wq, const float* __restrict__ Wo)
{
    if (blockIdx.z == 0) transpose_split_body(Wq, g_wqt_h, g_wqt_l, C_DIM, C_DIM);
    else                 transpose_split_body(Wo, g_wot_h, g_wot_l, C_DIM, C_DIM);
}

__global__ void transpose_kv_kernel(const float* __restrict__ Wk, const float* __restrict__ Wv)
{
    if (blockIdx.z == 0) transpose_split_body(Wk, g_wkt_h, g_wkt_l, C_DIM, NKV);
    else                 transpose_split_body(Wv, g_wvt_h, g_wvt_l, C_DIM, NKV);
}

// ---------------------------------------------------------------------------
// bf16x3 GEMM: 256x128 block tile, BK=64, 256 threads, 2-stage pipeline,
// one barrier per iteration.
// ---------------------------------------------------------------------------
#define G2_AH 0
#define G2_AL 32768
#define G2_BH 65536
#define G2_BL 81920
#define G2_STAGE 98304
#define G2_SMEM  (2 * G2_STAGE)

__device__ __forceinline__ void g_load_stage(uint32_t dstbase,
    const __nv_bfloat16* __restrict__ Ah, const __nv_bfloat16* __restrict__ Al,
    const __nv_bfloat16* __restrict__ Bh, const __nv_bfloat16* __restrict__ Bl,
    int bm, int bn, int k0, int K, int tid)
{
    const int row = tid >> 3;
    const int c   = tid & 7;
    const uint32_t swc = (uint32_t)((c ^ (row & 7)) << 4);
#pragma unroll
    for (int jj = 0; jj < 8; jj++) {
        int r = row + 32 * jj;
        uint32_t so = (uint32_t)r * 128 + swc;
        size_t ga = (size_t)(bm + r) * K + k0 + c * 8;
        cp_async16(dstbase + G2_AH + so, Ah + ga);
        cp_async16(dstbase + G2_AL + so, Al + ga);
    }
#pragma unroll
    for (int jj = 0; jj < 4; jj++) {
        int r = row + 32 * jj;
        uint32_t so = (uint32_t)r * 128 + swc;
        size_t gb = (size_t)(bn + r) * K + k0 + c * 8;
        cp_async16(dstbase + G2_BH + so, Bh + gb);
        cp_async16(dstbase + G2_BL + so, Bl + gb);
    }
}

__device__ void gemm_body(
    const __nv_bfloat16* __restrict__ Ah, const __nv_bfloat16* __restrict__ Al,
    const __nv_bfloat16* __restrict__ Bh, const __nv_bfloat16* __restrict__ Bl,
    float* __restrict__ C, __nv_bfloat16* __restrict__ Ch, __nv_bfloat16* __restrict__ Cl,
    int splitout, int M, int N, int K, int bxx, int byy)
{
    extern __shared__ char smg[];
    const int tid  = threadIdx.x;
    const int wid  = tid >> 5;
    const int lane = tid & 31;
    const int warp_m = wid & 3;
    const int warp_n = wid >> 2;
    const int bm = byy * 256;
    const int bn = bxx * 128;
    const uint32_t sbase = smem_u32(smg);

    const int ar  = (lane & 7) | (((lane >> 3) & 1) << 3);
    const int ag  = lane >> 4;
    const int ar7 = ar & 7;
    const int br  = (lane & 7) | ((lane >> 4) << 3);
    const int bg  = (lane >> 3) & 1;
    const int br7 = lane & 7;

    uint32_t a_ro[4], b_ro[4];
#pragma unroll
    for (int mi = 0; mi < 4; mi++)
        a_ro[mi] = (uint32_t)(warp_m * 64 + mi * 16 + ar) * 128 + G2_AH;
#pragma unroll
    for (int ng = 0; ng < 4; ng++)
        b_ro[ng] = (uint32_t)(warp_n * 64 + ng * 16 + br) * 128 + G2_BH;

    float acc[4][8][4];
#pragma unroll
    for (int mi = 0; mi < 4; mi++)
#pragma unroll
        for (int nf = 0; nf < 8; nf++)
#pragma unroll
            for (int e = 0; e < 4; e++) acc[mi][nf][e] = 0.0f;

    const int NK = K >> 6;

    g_load_stage(sbase, Ah, Al, Bh, Bl, bm, bn, 0, K, tid);
    cp_commit();

    for (int i = 0; i < NK; i++) {
        cp_wait<0>();
        __syncthreads();

        if (i + 1 < NK) {
            g_load_stage(sbase + ((i + 1) & 1) * G2_STAGE, Ah, Al, Bh, Bl,
                         bm, bn, (i + 1) * 64, K, tid);
            cp_commit();
        }

        const uint32_t stb = sbase + (i & 1) * G2_STAGE;
#pragma unroll
        for (int ks = 0; ks < 4; ks++) {
            const uint32_t cA = (uint32_t)(((ks * 2 + ag) ^ ar7) << 4);
            const uint32_t cB = (uint32_t)(((ks * 2 + bg) ^ br7) << 4);
            uint32_t ahi[4][4], alo[4][4];
#pragma unroll
            for (int mi = 0; mi < 4; mi++) {
                uint32_t ad = stb + a_ro[mi] + cA;
                LDMATRIX_X4(ahi[mi][0], ahi[mi][1], ahi[mi][2], ahi[mi][3], ad);
                LDMATRIX_X4(alo[mi][0], alo[mi][1], alo[mi][2], alo[mi][3], ad + 32768);
            }
            uint32_t bhi[4][4], blo[4][4];
#pragma unroll
            for (int ng = 0; ng < 4; ng++) {
                uint32_t bd = stb + b_ro[ng] + cB;
                LDMATRIX_X4(bhi[ng][0], bhi[ng][1], bhi[ng][2], bhi[ng][3], bd);
                LDMATRIX_X4(blo[ng][0], blo[ng][1], blo[ng][2], blo[ng][3], bd + 16384);
            }
#pragma unroll
            for (int mi = 0; mi < 4; mi++)
#pragma unroll
                for (int ng = 0; ng < 4; ng++) {
                    MMA_BF16(acc[mi][2*ng],   ahi[mi][0], ahi[mi][1], ahi[mi][2], ahi[mi][3], bhi[ng][0], bhi[ng][1]);
                    MMA_BF16(acc[mi][2*ng+1], ahi[mi][0], ahi[mi][1], ahi[mi][2], ahi[mi][3], bhi[ng][2], bhi[ng][3]);
                }
#pragma unroll
            for (int mi = 0; mi < 4; mi++)
#pragma unroll
                for (int ng = 0; ng < 4; ng++) {
                    MMA_BF16(acc[mi][2*ng],   ahi[mi][0], ahi[mi][1], ahi[mi][2], ahi[mi][3], blo[ng][0], blo[ng][1]);
                    MMA_BF16(acc[mi][2*ng+1], ahi[mi][0], ahi[mi][1], ahi[mi][2], ahi[mi][3], blo[ng][2], blo[ng][3]);
                }
#pragma unroll
            for (int mi = 0; mi < 4; mi++)
#pragma unroll
                for (int ng = 0; ng < 4; ng++) {
                    MMA_BF16(acc[mi][2*ng],   alo[mi][0], alo[mi][1], alo[mi][2], alo[mi][3], bhi[ng][0], bhi[ng][1]);
                    MMA_BF16(acc[mi][2*ng+1], alo[mi][0], alo[mi][1], alo[mi][2], alo[mi][3], bhi[ng][2], bhi[ng][3]);
                }
        }
    }

    const int trow = lane >> 2;
    const int tcol = (lane & 3) << 1;
#pragma unroll
    for (int mi = 0; mi < 4; mi++) {
#pragma unroll
        for (int nf = 0; nf < 8; nf++) {
            int rg = bm + warp_m * 64 + mi * 16 + trow;
            int cg = bn + warp_n * 64 + nf * 8 + tcol;
            if (!splitout) {
                *(float2*)&C[(size_t)rg * N + cg]       = make_float2(acc[mi][nf][0], acc[mi][nf][1]);
                *(float2*)&C[(size_t)(rg + 8) * N + cg] = make_float2(acc[mi][nf][2], acc[mi][nf][3]);
            } else {
                uint32_t hh, ll;
                split2(acc[mi][nf][0], acc[mi][nf][1], hh, ll);
                *(uint32_t*)&Ch[(size_t)rg * N + cg] = hh;
                *(uint32_t*)&Cl[(size_t)rg * N + cg] = ll;
                split2(acc[mi][nf][2], acc[mi][nf][3], hh, ll);
                *(uint32_t*)&Ch[(size_t)(rg + 8) * N + cg] = hh;
                *(uint32_t*)&Cl[(size_t)(rg + 8) * N + cg] = ll;
            }
        }
    }
}

__global__ __launch_bounds__(256)
void gemm_one(const __nv_bfloat16* Ah, const __nv_bfloat16* Al,
              const __nv_bfloat16* Bh, const __nv_bfloat16* Bl,
              float* C, int M, int N, int K)
{
    gemm_body(Ah, Al, Bh, Bl, C, nullptr, nullptr, 0, M, N, K, blockIdx.x, blockIdx.y);
}

__global__ __launch_bounds__(256)
void gemm_kv(const __nv_bfloat16* Ah, const __nv_bfloat16* Al, float* Kout)
{
    if (blockIdx.z == 0)
        gemm_body(Ah, Al, g_wkt_h, g_wkt_l, Kout, nullptr, nullptr, 0,
                  T_LEN, NKV, C_DIM, blockIdx.x, blockIdx.y);
    else
        gemm_body(Ah, Al, g_wvt_h, g_wvt_l, nullptr, g_vsh, g_vsl, 1,
                  T_LEN, NKV, C_DIM, blockIdx.x, blockIdx.y);
}

// ---------------------------------------------------------------------------
// RoPE
// ---------------------------------------------------------------------------
__global__ void rope_table_kernel()
{
    __shared__ float s_invf[64];
    if (threadIdx.x < 64) {
        double e = exp(-(double)threadIdx.x * (log(10000.0) / 64.0));
        s_invf[threadIdx.x] = (float)e;
    }
    __syncthreads();
    int idx = blockIdx.x * blockDim.x + threadIdx.x;
    if (idx >= T_LEN * 64) return;
    int t = idx >> 6;
    int j = idx & 63;
    float ang = (float)t * s_invf[j];
    float s, c;
    sincosf(ang, &s, &c);
    g_cos[idx] = c;
    g_sin[idx] = s;
}

// K-only RoPE apply + split (Q rope is fused into attention).
__global__ void rope_k_kernel(const float* __restrict__ K)
{
    int idx = blockIdx.x * blockDim.x + threadIdx.x;   // T*HKV*32 threads
    int t = idx >> 7;
    int rem = idx & 127;
    int h = rem >> 5;
    int j2 = (rem & 31) << 1;
    size_t o = (size_t)t * NKV + h * HD;
    const float* p = K + o;
    float2 x0 = *(const float2*)(p + j2);
    float2 x1 = *(const float2*)(p + j2 + 64);
    float2 cv = *(const float2*)(g_cos + t * 64 + j2);
    float2 sv = *(const float2*)(g_sin + t * 64 + j2);
    float r0a = x0.x * cv.x - x1.x * sv.x;
    float r0b = x0.y * cv.y - x1.y * sv.y;
    float r1a = x1.x * cv.x + x0.x * sv.x;
    float r1b = x1.y * cv.y + x0.y * sv.y;
    uint32_t hh, ll;
    split2(r0a, r0b, hh, ll);
    *(uint32_t*)&g_ksh[o + j2] = hh;
    *(uint32_t*)&g_ksl[o + j2] = ll;
    split2(r1a, r1b, hh, ll);
    *(uint32_t*)&g_ksh[o + j2 + 64] = hh;
    *(uint32_t*)&g_ksl[o + j2 + 64] = ll;
}

// ---------------------------------------------------------------------------
// Flash attention, GQA-packed (32 q x 4 heads / block, 64-key tiles, 256 thr).
// Q RoPE+scale+split fused into the fragment load (rotation is thread-local:
// pair (d, d+64) lives in fragments (ks, ks+4) of the same thread).
// Heavy blocks launched first (reversed qb) to pack the tail wave.
// ---------------------------------------------------------------------------
#define KVS   136
#define AR_SZ (64 * KVS * 2)
#define A_KH  0
#define A_KL  AR_SZ
#define A_VH  (2 * AR_SZ)
#define A_VL  (3 * AR_SZ)
#define ATT_STAGE (4 * AR_SZ)
#define ATT_SMEM  (2 * ATT_STAGE)

__device__ __forceinline__ void attn_load_kv(uint32_t dstbase, int jb, int kvh, int tid)
{
#pragma unroll
    for (int i = 0; i < 4; i++) {
        int idx = tid + 256 * i;
        int row = idx >> 4;
        int c16 = idx & 15;
        uint32_t so = (uint32_t)row * (KVS * 2) + c16 * 16;
        size_t g = (size_t)(jb + row) * NKV + kvh * HD + c16 * 8;
        cp_async16(dstbase + A_KH + so, g_ksh + g);
        cp_async16(dstbase + A_KL + so, g_ksl + g);
        cp_async16(dstbase + A_VH + so, g_vsh + g);
        cp_async16(dstbase + A_VL + so, g_vsl + g);
    }
}

__global__ __launch_bounds__(256)
void attn_tc_kernel(const float* __restrict__ Qf,
                    __nv_bfloat16* __restrict__ Yh, __nv_bfloat16* __restrict__ Yl)
{
    extern __shared__ char sma[];
    const uint32_t sbase = smem_u32(sma);

    const int qb  = gridDim.x - 1 - blockIdx.x;   // heavy blocks first
    const int kvh = blockIdx.y;
    const int tid  = threadIdx.x;
    const int wid  = tid >> 5;
    const int lane = tid & 31;
    const int trow = lane >> 2;
    const int tc2  = (lane & 3) << 1;

    const int q0    = qb * 32;
    const int head  = kvh * 4 + (wid >> 1);
    const int qbase = q0 + ((wid & 1) << 4);

    // Q fragments: load fp32, RoPE-rotate + scale + split in registers.
    uint32_t qhi[8][4], qlo[8][4];
#pragma unroll
    for (int ks = 0; ks < 4; ks++) {
#pragma unroll
        for (int r = 0; r < 4; r++) {
            int row = qbase + trow + ((r & 1) << 3);
            int j = ks * 16 + ((r >> 1) << 3) + tc2;   // 0..62
            const float* qp = Qf + (size_t)row * C_DIM + head * HD;
            float2 x0 = *(const float2*)(qp + j);
            float2 x1 = *(const float2*)(qp + j + 64);
            float2 cv = *(const float2*)(g_cos + row * 64 + j);
            float2 sv = *(const float2*)(g_sin + row * 64 + j);
            float r0a = (x0.x * cv.x - x1.x * sv.x) * SCQ_CONST;
            float r0b = (x0.y * cv.y - x1.y * sv.y) * SCQ_CONST;
            float r1a = (x1.x * cv.x + x0.x * sv.x) * SCQ_CONST;
            float r1b = (x1.y * cv.y + x0.y * sv.y) * SCQ_CONST;
            split2(r0a, r0b, qhi[ks][r],     qlo[ks][r]);
            split2(r1a, r1b, qhi[ks + 4][r], qlo[ks + 4][r]);
        }
    }

    float oacc[16][4];
#pragma unroll
    for (int nf = 0; nf < 16; nf++)
#pragma unroll
        for (int e = 0; e < 4; e++) oacc[nf][e] = 0.0f;
    float m2[2]   = { -1e30f, -1e30f };
    float lsum[2] = { 0.0f, 0.0f };

    int jmin = q0 - (WIN - 1);
    if (jmin < 0) jmin = 0;
    const int kb0 = jmin >> 6;
    const int kb1 = (q0 + 31) >> 6;

    const int krow    = (lane & 7) + ((lane >> 4) << 3);
    const int kcoloff = ((lane >> 3) & 1) << 3;
    const int vrow    = (lane & 7) + (((lane >> 3) & 1) << 3);
    const int vcoloff = (lane >> 4) << 3;

    const uint32_t kh_ro = (uint32_t)(krow * KVS + kcoloff) * 2;
    const uint32_t vh_ro = (uint32_t)(vrow * KVS + vcoloff) * 2;
    const uint32_t KROW16 = (uint32_t)(16 * KVS) * 2;

    attn_load_kv(sbase, kb0 * 64, kvh, tid);
    cp_commit();

    int s = 0;
    for (int kb = kb0; kb <= kb1; kb++) {
        const int jb = kb * 64;
        if (kb < kb1) {
            attn_load_kv(sbase + (s ^ 1) * ATT_STAGE, (kb + 1) * 64, kvh, tid);
            cp_commit();
            cp_wait<1>();
        } else {
            cp_wait<0>();
        }
        __syncthreads();

        const uint32_t stb = sbase + s * ATT_STAGE;
        const uint32_t kh_base = stb + A_KH + kh_ro;
        const uint32_t vh_base = stb + A_VH + vh_ro;
        const uint32_t vl_base = stb + A_VL + vh_ro;

        float sacc[8][4];
#pragma unroll
        for (int f = 0; f < 8; f++)
#pragma unroll
            for (int e = 0; e < 4; e++) sacc[f][e] = 0.0f;

#pragma unroll
        for (int ks = 0; ks < 8; ks++) {
            uint32_t off = (uint32_t)(ks * 16) * 2;
#pragma unroll
            for (int g = 0; g < 4; g++) {
                uint32_t bh[4], bl[4];
                uint32_t ad = kh_base + off + g * KROW16;
                LDMATRIX_X4(bh[0], bh[1], bh[2], bh[3], ad);
                LDMATRIX_X4(bl[0], bl[1], bl[2], bl[3], ad + AR_SZ);
                const int f0 = 2 * g, f1 = 2 * g + 1;
                MMA_BF16(sacc[f0], qhi[ks][0], qhi[ks][1], qhi[ks][2], qhi[ks][3], bh[0], bh[1]);
                MMA_BF16(sacc[f1], qhi[ks][0], qhi[ks][1], qhi[ks][2], qhi[ks][3], bh[2], bh[3]);
                MMA_BF16(sacc[f0], qlo[ks][0], qlo[ks][1], qlo[ks][2], qlo[ks][3], bh[0], bh[1]);
                MMA_BF16(sacc[f1], qlo[ks][0], qlo[ks][1], qlo[ks][2], qlo[ks][3], bh[2], bh[3]);
                MMA_BF16(sacc[f0], qhi[ks][0], qhi[ks][1], qhi[ks][2], qhi[ks][3], bl[0], bl[1]);
                MMA_BF16(sacc[f1], qhi[ks][0], qhi[ks][1], qhi[ks][2], qhi[ks][3], bl[2], bl[3]);
            }
        }

        const bool full = (jb + 64 <= q0) && (jb >= q0 - (WIN - 32));
        if (!full) {
#pragma unroll
            for (int f = 0; f < 8; f++) {
                int j0 = jb + f * 8 + tc2;
#pragma unroll
                for (int e = 0; e < 4; e++) {
                    int j  = j0 + (e & 1);
                    int qi = qbase + trow + ((e >> 1) << 3);
                    bool ok = (j <= qi) && ((qi - j) < WIN);
                    if (!ok) sacc[f][e] = -1e30f;
                }
            }
        }

        float bm0 = -1e30f, bm1 = -1e30f;
#pragma unroll
        for (int f = 0; f < 8; f++) {
            bm0 = fmaxf(bm0, fmaxf(sacc[f][0], sacc[f][1]));
            bm1 = fmaxf(bm1, fmaxf(sacc[f][2], sacc[f][3]));
        }
        bm0 = fmaxf(bm0, __shfl_xor_sync(0xffffffffu, bm0, 1));
        bm0 = fmaxf(bm0, __shfl_xor_sync(0xffffffffu, bm0, 2));
        bm1 = fmaxf(bm1, __shfl_xor_sync(0xffffffffu, bm1, 1));
        bm1 = fmaxf(bm1, __shfl_xor_sync(0xffffffffu, bm1, 2));

        float mn0 = fmaxf(m2[0], bm0);
        float mn1 = fmaxf(m2[1], bm1);
        float mm0 = fmaxf(mn0, -1e20f);
        float mm1 = fmaxf(mn1, -1e20f);
        float f0 = exp2f(m2[0] - mm0);
        float f1 = exp2f(m2[1] - mm1);
        m2[0] = mn0; m2[1] = mn1;

        float ps0 = 0.0f, ps1 = 0.0f;
#pragma unroll
        for (int f = 0; f < 8; f++) {
            sacc[f][0] = exp2f(sacc[f][0] - mm0);
            sacc[f][1] = exp2f(sacc[f][1] - mm0);
            sacc[f][2] = exp2f(sacc[f][2] - mm1);
            sacc[f][3] = exp2f(sacc[f][3] - mm1);
            ps0 += sacc[f][0] + sacc[f][1];
            ps1 += sacc[f][2] + sacc[f][3];
        }
        ps0 += __shfl_xor_sync(0xffffffffu, ps0, 1);
        ps0 += __shfl_xor_sync(0xffffffffu, ps0, 2);
        ps1 += __shfl_xor_sync(0xffffffffu, ps1, 1);
        ps1 += __shfl_xor_sync(0xffffffffu, ps1, 2);
        lsum[0] = lsum[0] * f0 + ps0;
        lsum[1] = lsum[1] * f1 + ps1;

#pragma unroll
        for (int nf = 0; nf < 16; nf++) {
            oacc[nf][0] *= f0; oacc[nf][1] *= f0;
            oacc[nf][2] *= f1; oacc[nf][3] *= f1;
        }

        uint32_t phi[4][4], plo[4][4];
#pragma unroll
        for (int kp = 0; kp < 4; kp++) {
            split2(sacc[2*kp][0],   sacc[2*kp][1],   phi[kp][0], plo[kp][0]);
            split2(sacc[2*kp][2],   sacc[2*kp][3],   phi[kp][1], plo[kp][1]);
            split2(sacc[2*kp+1][0], sacc[2*kp+1][1], phi[kp][2], plo[kp][2]);
            split2(sacc[2*kp+1][2], sacc[2*kp+1][3], phi[kp][3], plo[kp][3]);
        }

#pragma unroll
        for (int kp = 0; kp < 4; kp++) {
            uint32_t rowoff = (uint32_t)(kp * 16 * KVS) * 2;
#pragma unroll
            for (int ng = 0; ng < 8; ng++) {
                uint32_t coff = rowoff + (uint32_t)(ng * 16) * 2;
                uint32_t vh4[4], vl4[4];
                LDMATRIX_X4_T(vh4[0], vh4[1], vh4[2], vh4[3], vh_base + coff);
                LDMATRIX_X4_T(vl4[0], vl4[1], vl4[2], vl4[3], vl_base + coff);
                MMA_BF16(oacc[2*ng],   phi[kp][0], phi[kp][1], phi[kp][2], phi[kp][3], vh4[0], vh4[1]);
                MMA_BF16(oacc[2*ng+1], phi[kp][0], phi[kp][1], phi[kp][2], phi[kp][3], vh4[2], vh4[3]);
                MMA_BF16(oacc[2*ng],   plo[kp][0], plo[kp][1], plo[kp][2], plo[kp][3], vh4[0], vh4[1]);
                MMA_BF16(oacc[2*ng+1], plo[kp][0], plo[kp][1], plo[kp][2], plo[kp][3], vh4[2], vh4[3]);
                MMA_BF16(oacc[2*ng],   phi[kp][0], phi[kp][1], phi[kp][2], phi[kp][3], vl4[0], vl4[1]);
                MMA_BF16(oacc[2*ng+1], phi[kp][0], phi[kp][1], phi[kp][2], phi[kp][3], vl4[2], vl4[3]);
            }
        }
        __syncthreads();
        s ^= 1;
    }

    float il0 = 1.0f / lsum[0];
    float il1 = 1.0f / lsum[1];
    const int row0 = qbase + trow;
#pragma unroll
    for (int nf = 0; nf < 16; nf++) {
        int col = head * HD + nf * 8 + tc2;
        uint32_t hh, ll;
        split2(oacc[nf][0] * il0, oacc[nf][1] * il0, hh, ll);
        *(uint32_t*)&Yh[(size_t)row0 * C_DIM + col] = hh;
        *(uint32_t*)&Yl[(size_t)row0 * C_DIM + col] = ll;
        split2(oacc[nf][2] * il1, oacc[nf][3] * il1, hh, ll);
        *(uint32_t*)&Yh[(size_t)(row0 + 8) * C_DIM + col] = hh;
        *(uint32_t*)&Yl[(size_t)(row0 + 8) * C_DIM + col] = ll;
    }
}

// ---------------------------------------------------------------------------
// Launch (position #4 = Wq GEMM for ncu capture)
// ---------------------------------------------------------------------------
extern "C" void kernel_launch(void* const* d_in, const int* in_sizes, int n_in,
                              void* d_out, int out_size)
{
    const float* x  = (const float*)d_in[0];
    const float* Wq = (const float*)d_in[1];
    const float* Wk = (const float*)d_in[2];
    const float* Wv = (const float*)d_in[3];
    const float* Wo = (const float*)d_in[4];
    float* out = (float*)d_out;

    float *Q, *Kp;
    cudaGetSymbolAddress((void**)&Q,  g_Q);
    cudaGetSymbolAddress((void**)&Kp, g_K);

    __nv_bfloat16 *xh, *xl, *yh, *yl, *wqh, *wql, *woh, *wol;
    cudaGetSymbolAddress((void**)&xh, g_xh);
    cudaGetSymbolAddress((void**)&xl, g_xl);
    cudaGetSymbolAddress((void**)&yh, g_yh);
    cudaGetSymbolAddress((void**)&yl, g_yl);
    cudaGetSymbolAddress((void**)&wqh, g_wqt_h);
    cudaGetSymbolAddress((void**)&wql, g_wqt_l);
    cudaGetSymbolAddress((void**)&woh, g_wot_h);
    cudaGetSymbolAddress((void**)&wol, g_wot_l);

    static bool attr_done = false;
    if (!attr_done) {
        cudaFuncSetAttribute(gemm_one, cudaFuncAttributeMaxDynamicSharedMemorySize, G2_SMEM);
        cudaFuncSetAttribute(gemm_kv,  cudaFuncAttributeMaxDynamicSharedMemorySize, G2_SMEM);
        cudaFuncSetAttribute(attn_tc_kernel, cudaFuncAttributeMaxDynamicSharedMemorySize, ATT_SMEM);
        attr_done = true;
    }

    // 1: RoPE table
    rope_table_kernel<<<(T_LEN * 64) / 256, 256>>>();
    // 2: split x
    split_f32_kernel<<<(T_LEN * C_DIM / 4 + 255) / 256, 256>>>(x, xh, xl, T_LEN * C_DIM / 4);
    // 3: transpose Wq + Wo
    transpose_qo_kernel<<<dim3(C_DIM / 32, C_DIM / 32, 2), dim3(32, 8)>>>(Wq, Wo);
    // 4: Q projection  <-- profiled launch
    gemm_one<<<dim3((HQ * HD) / 128, T_LEN / 256), 256, G2_SMEM>>>(xh, xl, wqh, wql, Q, T_LEN, HQ * HD, C_DIM);
    // 5: transpose Wk + Wv
    transpose_kv_kernel<<<dim3(NKV / 32, C_DIM / 32, 2), dim3(32, 8)>>>(Wk, Wv);
    // 6: K + V projections
    gemm_kv<<<dim3(NKV / 128, T_LEN / 256, 2), 256, G2_SMEM>>>(xh, xl, Kp);
    // 7: K RoPE + split (Q rope fused into attention)
    rope_k_kernel<<<(T_LEN * HKV * 32) / 256, 256>>>(Kp);
    // 8: attention (GQA-packed, Q-rope fused, heavy blocks first)
    attn_tc_kernel<<<dim3(T_LEN / 32, HKV), 256, ATT_SMEM>>>(Q, yh, yl);
    // 9: output projection
    gemm_one<<<dim3(C_DIM / 128, T_LEN / 256), 256, G2_SMEM>>>(yh, yl, woh, wol, out, T_LEN, C_DIM, C_DIM);
}

// round 15
// speedup vs baseline: 1.0827x; 1.0065x over previous
#include <cuda_runtime.h>
#include <cuda_bf16.h>
#include <math.h>
#include <float.h>
#include <stdint.h>

// Problem constants
#define T_LEN   4096
#define C_DIM   2048
#define HQ      16
#define HKV     4
#define HD      128
#define WIN     1024
#define NKV     (HKV * HD)     // 512

#define SCQ_CONST 0.1275174541395871f  // 1/sqrt(128) * log2(e)

// fp32 scratch
__device__ float g_Q[T_LEN * HQ * HD];
__device__ float g_K[T_LEN * NKV];
__device__ float g_cos[T_LEN * 64];
__device__ float g_sin[T_LEN * 64];

// bf16 split operands
__device__ __nv_bfloat16 g_xh[T_LEN * C_DIM],  g_xl[T_LEN * C_DIM];
__device__ __nv_bfloat16 g_yh[T_LEN * C_DIM],  g_yl[T_LEN * C_DIM];
__device__ __nv_bfloat16 g_ksh[T_LEN * NKV],   g_ksl[T_LEN * NKV];
__device__ __nv_bfloat16 g_vsh[T_LEN * NKV],   g_vsl[T_LEN * NKV];
__device__ __nv_bfloat16 g_wqt_h[C_DIM * C_DIM], g_wqt_l[C_DIM * C_DIM];
__device__ __nv_bfloat16 g_wkt_h[NKV * C_DIM],   g_wkt_l[NKV * C_DIM];
__device__ __nv_bfloat16 g_wvt_h[NKV * C_DIM],   g_wvt_l[NKV * C_DIM];
__device__ __nv_bfloat16 g_wot_h[C_DIM * C_DIM], g_wot_l[C_DIM * C_DIM];

// ---------------------------------------------------------------------------
// helpers
// ---------------------------------------------------------------------------
__device__ __forceinline__ uint32_t smem_u32(const void* p) {
    return (uint32_t)__cvta_generic_to_shared(p);
}

__device__ __forceinline__ void split2(float a, float b, uint32_t& hi, uint32_t& lo) {
    __nv_bfloat16 ah = __float2bfloat16_rn(a);
    __nv_bfloat16 bh = __float2bfloat16_rn(b);
    __nv_bfloat162 h(ah, bh);
    hi = *(uint32_t*)&h;
    __nv_bfloat162 l(__float2bfloat16_rn(a - __bfloat162float(ah)),
                     __float2bfloat16_rn(b - __bfloat162float(bh)));
    lo = *(uint32_t*)&l;
}

#define LDMATRIX_X4(R0,R1,R2,R3,ADDR) \
    asm volatile("ldmatrix.sync.aligned.m8n8.x4.shared.b16 {%0,%1,%2,%3}, [%4];" \
        : "=r"(R0), "=r"(R1), "=r"(R2), "=r"(R3) : "r"(ADDR))

#define LDMATRIX_X4_T(R0,R1,R2,R3,ADDR) \
    asm volatile("ldmatrix.sync.aligned.m8n8.x4.trans.shared.b16 {%0,%1,%2,%3}, [%4];" \
        : "=r"(R0), "=r"(R1), "=r"(R2), "=r"(R3) : "r"(ADDR))

#define MMA_BF16(D, A0,A1,A2,A3, B0,B1) \
    asm volatile("mma.sync.aligned.m16n8k16.row.col.f32.bf16.bf16.f32 " \
        "{%0,%1,%2,%3}, {%4,%5,%6,%7}, {%8,%9}, {%0,%1,%2,%3};" \
        : "+f"((D)[0]), "+f"((D)[1]), "+f"((D)[2]), "+f"((D)[3]) \
        : "r"(A0), "r"(A1), "r"(A2), "r"(A3), "r"(B0), "r"(B1))

__device__ __forceinline__ void cp_async16(uint32_t dst, const void* src) {
    asm volatile("cp.async.cg.shared.global [%0], [%1], 16;" :: "r"(dst), "l"(src));
}
__device__ __forceinline__ void cp_commit() {
    asm volatile("cp.async.commit_group;" ::: "memory");
}
template <int NN> __device__ __forceinline__ void cp_wait() {
    asm volatile("cp.async.wait_group %0;" :: "n"(NN) : "memory");
}

// ---------------------------------------------------------------------------
// Merged prep: z=0 Wq-T, z=1 Wo-T, z=2 Wk-T, z=3 Wv-T, z=4,5 split x,
// z=6 rope table. Block (32,8).
// ---------------------------------------------------------------------------
__device__ __forceinline__ void transpose_split_body(
    const float* __restrict__ W, __nv_bfloat16* __restrict__ Th,
    __nv_bfloat16* __restrict__ Tl, int Kd, int Nd, int bx, int by)
{
    __shared__ float tile[32][33];
    const int x = threadIdx.x;
    const int y = threadIdx.y;
#pragma unroll
    for (int j = 0; j < 32; j += 8)
        tile[y + j][x] = W[(size_t)(by * 32 + y + j) * Nd + bx * 32 + x];
    __syncthreads();
#pragma unroll
    for (int j = 0; j < 32; j += 8) {
        float v = tile[x][y + j];
        __nv_bfloat16 h = __float2bfloat16_rn(v);
        size_t o = (size_t)(bx * 32 + y + j) * Kd + by * 32 + x;
        Th[o] = h;
        Tl[o] = __float2bfloat16_rn(v - __bfloat162float(h));
    }
}

__global__ void prep_all(const float* __restrict__ x,
                         const float* __restrict__ Wq, const float* __restrict__ Wk,
                         const float* __restrict__ Wv, const float* __restrict__ Wo)
{
    const int z = blockIdx.z, bx = blockIdx.x, by = blockIdx.y;
    const int tid = threadIdx.y * 32 + threadIdx.x;
    if (z == 0)       transpose_split_body(Wq, g_wqt_h, g_wqt_l, C_DIM, C_DIM, bx, by);
    else if (z == 1)  transpose_split_body(Wo, g_wot_h, g_wot_l, C_DIM, C_DIM, bx, by);
    else if (z == 2) { if (bx < 16) transpose_split_body(Wk, g_wkt_h, g_wkt_l, C_DIM, NKV, bx, by); }
    else if (z == 3) { if (bx < 16) transpose_split_body(Wv, g_wvt_h, g_wvt_l, C_DIM, NKV, bx, by); }
    else if (z <= 5) {
        int i = ((z - 4) * 4096 + by * 64 + bx) * 256 + tid;   // 2M float4 total
        float4 v = ((const float4*)x)[i];
        uint32_t h0, l0, h1, l1;
        split2(v.x, v.y, h0, l0);
        split2(v.z, v.w, h1, l1);
        ((uint2*)g_xh)[i] = make_uint2(h0, h1);
        ((uint2*)g_xl)[i] = make_uint2(l0, l1);
    } else {
        if (by >= 16) return;                     // 16*64 = 1024 blocks used
        __shared__ float s_invf[64];
        if (tid < 64) {
            double e = exp(-(double)tid * (log(10000.0) / 64.0));
            s_invf[tid] = (float)e;
        }
        __syncthreads();
        int idx = (by * 64 + bx) * 256 + tid;     // < T_LEN*64
        int t = idx >> 6;
        int j = idx & 63;
        float ang = (float)t * s_invf[j];
        float s, c;
        sincosf(ang, &s, &c);
        g_cos[idx] = c;
        g_sin[idx] = s;
    }
}

// ---------------------------------------------------------------------------
// bf16x3 GEMM: 256x128 block tile, BK=64, 256 threads, 2-stage pipeline,
// one barrier per iteration.
// ---------------------------------------------------------------------------
#define G2_AH 0
#define G2_AL 32768
#define G2_BH 65536
#define G2_BL 81920
#define G2_STAGE 98304
#define G2_SMEM  (2 * G2_STAGE)

__device__ __forceinline__ void g_load_stage(uint32_t dstbase,
    const __nv_bfloat16* __restrict__ Ah, const __nv_bfloat16* __restrict__ Al,
    const __nv_bfloat16* __restrict__ Bh, const __nv_bfloat16* __restrict__ Bl,
    int bm, int bn, int k0, int K, int tid)
{
    const int row = tid >> 3;
    const int c   = tid & 7;
    const uint32_t swc = (uint32_t)((c ^ (row & 7)) << 4);
#pragma unroll
    for (int jj = 0; jj < 8; jj++) {
        int r = row + 32 * jj;
        uint32_t so = (uint32_t)r * 128 + swc;
        size_t ga = (size_t)(bm + r) * K + k0 + c * 8;
        cp_async16(dstbase + G2_AH + so, Ah + ga);
        cp_async16(dstbase + G2_AL + so, Al + ga);
    }
#pragma unroll
    for (int jj = 0; jj < 4; jj++) {
        int r = row + 32 * jj;
        uint32_t so = (uint32_t)r * 128 + swc;
        size_t gb = (size_t)(bn + r) * K + k0 + c * 8;
        cp_async16(dstbase + G2_BH + so, Bh + gb);
        cp_async16(dstbase + G2_BL + so, Bl + gb);
    }
}

__device__ void gemm_body(
    const __nv_bfloat16* __restrict__ Ah, const __nv_bfloat16* __restrict__ Al,
    const __nv_bfloat16* __restrict__ Bh, const __nv_bfloat16* __restrict__ Bl,
    float* __restrict__ C, __nv_bfloat16* __restrict__ Ch, __nv_bfloat16* __restrict__ Cl,
    int splitout, int M, int N, int K, int bxx, int byy)
{
    extern __shared__ char smg[];
    const int tid  = threadIdx.x;
    const int wid  = tid >> 5;
    const int lane = tid & 31;
    const int warp_m = wid & 3;
    const int warp_n = wid >> 2;
    const int bm = byy * 256;
    const int bn = bxx * 128;
    const uint32_t sbase = smem_u32(smg);

    const int ar  = (lane & 7) | (((lane >> 3) & 1) << 3);
    const int ag  = lane >> 4;
    const int ar7 = ar & 7;
    const int br  = (lane & 7) | ((lane >> 4) << 3);
    const int bg  = (lane >> 3) & 1;
    const int br7 = lane & 7;

    uint32_t a_ro[4], b_ro[4];
#pragma unroll
    for (int mi = 0; mi < 4; mi++)
        a_ro[mi] = (uint32_t)(warp_m * 64 + mi * 16 + ar) * 128 + G2_AH;
#pragma unroll
    for (int ng = 0; ng < 4; ng++)
        b_ro[ng] = (uint32_t)(warp_n * 64 + ng * 16 + br) * 128 + G2_BH;

    float acc[4][8][4];
#pragma unroll
    for (int mi = 0; mi < 4; mi++)
#pragma unroll
        for (int nf = 0; nf < 8; nf++)
#pragma unroll
            for (int e = 0; e < 4; e++) acc[mi][nf][e] = 0.0f;

    const int NK = K >> 6;

    g_load_stage(sbase, Ah, Al, Bh, Bl, bm, bn, 0, K, tid);
    cp_commit();

    for (int i = 0; i < NK; i++) {
        cp_wait<0>();
        __syncthreads();

        if (i + 1 < NK) {
            g_load_stage(sbase + ((i + 1) & 1) * G2_STAGE, Ah, Al, Bh, Bl,
                         bm, bn, (i + 1) * 64, K, tid);
            cp_commit();
        }

        const uint32_t stb = sbase + (i & 1) * G2_STAGE;
#pragma unroll
        for (int ks = 0; ks < 4; ks++) {
            const uint32_t cA = (uint32_t)(((ks * 2 + ag) ^ ar7) << 4);
            const uint32_t cB = (uint32_t)(((ks * 2 + bg) ^ br7) << 4);
            uint32_t ahi[4][4], alo[4][4];
#pragma unroll
            for (int mi = 0; mi < 4; mi++) {
                uint32_t ad = stb + a_ro[mi] + cA;
                LDMATRIX_X4(ahi[mi][0], ahi[mi][1], ahi[mi][2], ahi[mi][3], ad);
                LDMATRIX_X4(alo[mi][0], alo[mi][1], alo[mi][2], alo[mi][3], ad + 32768);
            }
            uint32_t bhi[4][4], blo[4][4];
#pragma unroll
            for (int ng = 0; ng < 4; ng++) {
                uint32_t bd = stb + b_ro[ng] + cB;
                LDMATRIX_X4(bhi[ng][0], bhi[ng][1], bhi[ng][2], bhi[ng][3], bd);
                LDMATRIX_X4(blo[ng][0], blo[ng][1], blo[ng][2], blo[ng][3], bd + 16384);
            }
#pragma unroll
            for (int mi = 0; mi < 4; mi++)
#pragma unroll
                for (int ng = 0; ng < 4; ng++) {
                    MMA_BF16(acc[mi][2*ng],   ahi[mi][0], ahi[mi][1], ahi[mi][2], ahi[mi][3], bhi[ng][0], bhi[ng][1]);
                    MMA_BF16(acc[mi][2*ng+1], ahi[mi][0], ahi[mi][1], ahi[mi][2], ahi[mi][3], bhi[ng][2], bhi[ng][3]);
                }
#pragma unroll
            for (int mi = 0; mi < 4; mi++)
#pragma unroll
                for (int ng = 0; ng < 4; ng++) {
                    MMA_BF16(acc[mi][2*ng],   ahi[mi][0], ahi[mi][1], ahi[mi][2], ahi[mi][3], blo[ng][0], blo[ng][1]);
                    MMA_BF16(acc[mi][2*ng+1], ahi[mi][0], ahi[mi][1], ahi[mi][2], ahi[mi][3], blo[ng][2], blo[ng][3]);
                }
#pragma unroll
            for (int mi = 0; mi < 4; mi++)
#pragma unroll
                for (int ng = 0; ng < 4; ng++) {
                    MMA_BF16(acc[mi][2*ng],   alo[mi][0], alo[mi][1], alo[mi][2], alo[mi][3], bhi[ng][0], bhi[ng][1]);
                    MMA_BF16(acc[mi][2*ng+1], alo[mi][0], alo[mi][1], alo[mi][2], alo[mi][3], bhi[ng][2], bhi[ng][3]);
                }
        }
    }

    const int trow = lane >> 2;
    const int tcol = (lane & 3) << 1;
#pragma unroll
    for (int mi = 0; mi < 4; mi++) {
#pragma unroll
        for (int nf = 0; nf < 8; nf++) {
            int rg = bm + warp_m * 64 + mi * 16 + trow;
            int cg = bn + warp_n * 64 + nf * 8 + tcol;
            if (!splitout) {
                *(float2*)&C[(size_t)rg * N + cg]       = make_float2(acc[mi][nf][0], acc[mi][nf][1]);
                *(float2*)&C[(size_t)(rg + 8) * N + cg] = make_float2(acc[mi][nf][2], acc[mi][nf][3]);
            } else {
                uint32_t hh, ll;
                split2(acc[mi][nf][0], acc[mi][nf][1], hh, ll);
                *(uint32_t*)&Ch[(size_t)rg * N + cg] = hh;
                *(uint32_t*)&Cl[(size_t)rg * N + cg] = ll;
                split2(acc[mi][nf][2], acc[mi][nf][3], hh, ll);
                *(uint32_t*)&Ch[(size_t)(rg + 8) * N + cg] = hh;
                *(uint32_t*)&Cl[(size_t)(rg + 8) * N + cg] = ll;
            }
        }
    }
}

// Packed QKV: grid (24, 16). bx<16 -> Q (fp32), 16..19 -> K (fp32),
// 20..23 -> V (split bf16). No idle blocks; single launch fills 3 waves.
__global__ __launch_bounds__(256)
void gemm_qkv(const __nv_bfloat16* __restrict__ xh, const __nv_bfloat16* __restrict__ xl,
              float* __restrict__ Qout, float* __restrict__ Kout)
{
    const int bx = blockIdx.x;
    if (bx < 16)
        gemm_body(xh, xl, g_wqt_h, g_wqt_l, Qout, nullptr, nullptr, 0,
                  T_LEN, HQ * HD, C_DIM, bx, blockIdx.y);
    else if (bx < 20)
        gemm_body(xh, xl, g_wkt_h, g_wkt_l, Kout, nullptr, nullptr, 0,
                  T_LEN, NKV, C_DIM, bx - 16, blockIdx.y);
    else
        gemm_body(xh, xl, g_wvt_h, g_wvt_l, nullptr, g_vsh, g_vsl, 1,
                  T_LEN, NKV, C_DIM, bx - 20, blockIdx.y);
}

__global__ __launch_bounds__(256)
void gemm_one(const __nv_bfloat16* Ah, const __nv_bfloat16* Al,
              const __nv_bfloat16* Bh, const __nv_bfloat16* Bl,
              float* C, int M, int N, int K)
{
    gemm_body(Ah, Al, Bh, Bl, C, nullptr, nullptr, 0, M, N, K, blockIdx.x, blockIdx.y);
}

// ---------------------------------------------------------------------------
// K-only RoPE apply + split (Q rope fused into attention).
// ---------------------------------------------------------------------------
__global__ void rope_k_kernel(const float* __restrict__ K)
{
    int idx = blockIdx.x * blockDim.x + threadIdx.x;
    int t = idx >> 7;
    int rem = idx & 127;
    int h = rem >> 5;
    int j2 = (rem & 31) << 1;
    size_t o = (size_t)t * NKV + h * HD;
    const float* p = K + o;
    float2 x0 = *(const float2*)(p + j2);
    float2 x1 = *(const float2*)(p + j2 + 64);
    float2 cv = *(const float2*)(g_cos + t * 64 + j2);
    float2 sv = *(const float2*)(g_sin + t * 64 + j2);
    float r0a = x0.x * cv.x - x1.x * sv.x;
    float r0b = x0.y * cv.y - x1.y * sv.y;
    float r1a = x1.x * cv.x + x0.x * sv.x;
    float r1b = x1.y * cv.y + x0.y * sv.y;
    uint32_t hh, ll;
    split2(r0a, r0b, hh, ll);
    *(uint32_t*)&g_ksh[o + j2] = hh;
    *(uint32_t*)&g_ksl[o + j2] = ll;
    split2(r1a, r1b, hh, ll);
    *(uint32_t*)&g_ksh[o + j2 + 64] = hh;
    *(uint32_t*)&g_ksl[o + j2 + 64] = ll;
}

// ---------------------------------------------------------------------------
// Flash attention, GQA-packed (32 q x 4 heads / block, 64-key tiles, 256 thr),
// Q RoPE+scale+split fused into the fragment load, heavy blocks first.
// ---------------------------------------------------------------------------
#define KVS   136
#define AR_SZ (64 * KVS * 2)
#define A_KH  0
#define A_KL  AR_SZ
#define A_VH  (2 * AR_SZ)
#define A_VL  (3 * AR_SZ)
#define ATT_STAGE (4 * AR_SZ)
#define ATT_SMEM  (2 * ATT_STAGE)

__device__ __forceinline__ void attn_load_kv(uint32_t dstbase, int jb, int kvh, int tid)
{
#pragma unroll
    for (int i = 0; i < 4; i++) {
        int idx = tid + 256 * i;
        int row = idx >> 4;
        int c16 = idx & 15;
        uint32_t so = (uint32_t)row * (KVS * 2) + c16 * 16;
        size_t g = (size_t)(jb + row) * NKV + kvh * HD + c16 * 8;
        cp_async16(dstbase + A_KH + so, g_ksh + g);
        cp_async16(dstbase + A_KL + so, g_ksl + g);
        cp_async16(dstbase + A_VH + so, g_vsh + g);
        cp_async16(dstbase + A_VL + so, g_vsl + g);
    }
}

__global__ __launch_bounds__(256)
void attn_tc_kernel(const float* __restrict__ Qf,
                    __nv_bfloat16* __restrict__ Yh, __nv_bfloat16* __restrict__ Yl)
{
    extern __shared__ char sma[];
    const uint32_t sbase = smem_u32(sma);

    const int qb  = gridDim.x - 1 - blockIdx.x;   // heavy blocks first
    const int kvh = blockIdx.y;
    const int tid  = threadIdx.x;
    const int wid  = tid >> 5;
    const int lane = tid & 31;
    const int trow = lane >> 2;
    const int tc2  = (lane & 3) << 1;

    const int q0    = qb * 32;
    const int head  = kvh * 4 + (wid >> 1);
    const int qbase = q0 + ((wid & 1) << 4);

    // Q fragments: fp32 load, RoPE rotate + scale + split in registers.
    uint32_t qhi[8][4], qlo[8][4];
#pragma unroll
    for (int ks = 0; ks < 4; ks++) {
#pragma unroll
        for (int r = 0; r < 4; r++) {
            int row = qbase + trow + ((r & 1) << 3);
            int j = ks * 16 + ((r >> 1) << 3) + tc2;
            const float* qp = Qf + (size_t)row * C_DIM + head * HD;
            float2 x0 = *(const float2*)(qp + j);
            float2 x1 = *(const float2*)(qp + j + 64);
            float2 cv = *(const float2*)(g_cos + row * 64 + j);
            float2 sv = *(const float2*)(g_sin + row * 64 + j);
            float r0a = (x0.x * cv.x - x1.x * sv.x) * SCQ_CONST;
            float r0b = (x0.y * cv.y - x1.y * sv.y) * SCQ_CONST;
            float r1a = (x1.x * cv.x + x0.x * sv.x) * SCQ_CONST;
            float r1b = (x1.y * cv.y + x0.y * sv.y) * SCQ_CONST;
            split2(r0a, r0b, qhi[ks][r],     qlo[ks][r]);
            split2(r1a, r1b, qhi[ks + 4][r], qlo[ks + 4][r]);
        }
    }

    float oacc[16][4];
#pragma unroll
    for (int nf = 0; nf < 16; nf++)
#pragma unroll
        for (int e = 0; e < 4; e++) oacc[nf][e] = 0.0f;
    float m2[2]   = { -1e30f, -1e30f };
    float lsum[2] = { 0.0f, 0.0f };

    int jmin = q0 - (WIN - 1);
    if (jmin < 0) jmin = 0;
    const int kb0 = jmin >> 6;
    const int kb1 = (q0 + 31) >> 6;

    const int krow    = (lane & 7) + ((lane >> 4) << 3);
    const int kcoloff = ((lane >> 3) & 1) << 3;
    const int vrow    = (lane & 7) + (((lane >> 3) & 1) << 3);
    const int vcoloff = (lane >> 4) << 3;

    const uint32_t kh_ro = (uint32_t)(krow * KVS + kcoloff) * 2;
    const uint32_t vh_ro = (uint32_t)(vrow * KVS + vcoloff) * 2;
    const uint32_t KROW16 = (uint32_t)(16 * KVS) * 2;

    attn_load_kv(sbase, kb0 * 64, kvh, tid);
    cp_commit();

    int s = 0;
    for (int kb = kb0; kb <= kb1; kb++) {
        const int jb = kb * 64;
        if (kb < kb1) {
            attn_load_kv(sbase + (s ^ 1) * ATT_STAGE, (kb + 1) * 64, kvh, tid);
            cp_commit();
            cp_wait<1>();
        } else {
            cp_wait<0>();
        }
        __syncthreads();

        const uint32_t stb = sbase + s * ATT_STAGE;
        const uint32_t kh_base = stb + A_KH + kh_ro;
        const uint32_t vh_base = stb + A_VH + vh_ro;
        const uint32_t vl_base = stb + A_VL + vh_ro;

        float sacc[8][4];
#pragma unroll
        for (int f = 0; f < 8; f++)
#pragma unroll
            for (int e = 0; e < 4; e++) sacc[f][e] = 0.0f;

#pragma unroll
        for (int ks = 0; ks < 8; ks++) {
            uint32_t off = (uint32_t)(ks * 16) * 2;
#pragma unroll
            for (int g = 0; g < 4; g++) {
                uint32_t bh[4], bl[4];
                uint32_t ad = kh_base + off + g * KROW16;
                LDMATRIX_X4(bh[0], bh[1], bh[2], bh[3], ad);
                LDMATRIX_X4(bl[0], bl[1], bl[2], bl[3], ad + AR_SZ);
                const int f0 = 2 * g, f1 = 2 * g + 1;
                MMA_BF16(sacc[f0], qhi[ks][0], qhi[ks][1], qhi[ks][2], qhi[ks][3], bh[0], bh[1]);
                MMA_BF16(sacc[f1], qhi[ks][0], qhi[ks][1], qhi[ks][2], qhi[ks][3], bh[2], bh[3]);
                MMA_BF16(sacc[f0], qlo[ks][0], qlo[ks][1], qlo[ks][2], qlo[ks][3], bh[0], bh[1]);
                MMA_BF16(sacc[f1], qlo[ks][0], qlo[ks][1], qlo[ks][2], qlo[ks][3], bh[2], bh[3]);
                MMA_BF16(sacc[f0], qhi[ks][0], qhi[ks][1], qhi[ks][2], qhi[ks][3], bl[0], bl[1]);
                MMA_BF16(sacc[f1], qhi[ks][0], qhi[ks][1], qhi[ks][2], qhi[ks][3], bl[2], bl[3]);
            }
        }

        const bool full = (jb + 64 <= q0) && (jb >= q0 - (WIN - 32));
        if (!full) {
#pragma unroll
            for (int f = 0; f < 8; f++) {
                int j0 = jb + f * 8 + tc2;
#pragma unroll
                for (int e = 0; e < 4; e++) {
                    int j  = j0 + (e & 1);
                    int qi = qbase + trow + ((e >> 1) << 3);
                    bool ok = (j <= qi) && ((qi - j) < WIN);
                    if (!ok) sacc[f][e] = -1e30f;
                }
            }
        }

        float bm0 = -1e30f, bm1 = -1e30f;
#pragma unroll
        for (int f = 0; f < 8; f++) {
            bm0 = fmaxf(bm0, fmaxf(sacc[f][0], sacc[f][1]));
            bm1 = fmaxf(bm1, fmaxf(sacc[f][2], sacc[f][3]));
        }
        bm0 = fmaxf(bm0, __shfl_xor_sync(0xffffffffu, bm0, 1));
        bm0 = fmaxf(bm0, __shfl_xor_sync(0xffffffffu, bm0, 2));
        bm1 = fmaxf(bm1, __shfl_xor_sync(0xffffffffu, bm1, 1));
        bm1 = fmaxf(bm1, __shfl_xor_sync(0xffffffffu, bm1, 2));

        float mn0 = fmaxf(m2[0], bm0);
        float mn1 = fmaxf(m2[1], bm1);
        float mm0 = fmaxf(mn0, -1e20f);
        float mm1 = fmaxf(mn1, -1e20f);
        float f0 = exp2f(m2[0] - mm0);
        float f1 = exp2f(m2[1] - mm1);
        m2[0] = mn0; m2[1] = mn1;

        float ps0 = 0.0f, ps1 = 0.0f;
#pragma unroll
        for (int f = 0; f < 8; f++) {
            sacc[f][0] = exp2f(sacc[f][0] - mm0);
            sacc[f][1] = exp2f(sacc[f][1] - mm0);
            sacc[f][2] = exp2f(sacc[f][2] - mm1);
            sacc[f][3] = exp2f(sacc[f][3] - mm1);
            ps0 += sacc[f][0] + sacc[f][1];
            ps1 += sacc[f][2] + sacc[f][3];
        }
        ps0 += __shfl_xor_sync(0xffffffffu, ps0, 1);
        ps0 += __shfl_xor_sync(0xffffffffu, ps0, 2);
        ps1 += __shfl_xor_sync(0xffffffffu, ps1, 1);
        ps1 += __shfl_xor_sync(0xffffffffu, ps1, 2);
        lsum[0] = lsum[0] * f0 + ps0;
        lsum[1] = lsum[1] * f1 + ps1;

#pragma unroll
        for (int nf = 0; nf < 16; nf++) {
            oacc[nf][0] *= f0; oacc[nf][1] *= f0;
            oacc[nf][2] *= f1; oacc[nf][3] *= f1;
        }

        uint32_t phi[4][4], plo[4][4];
#pragma unroll
        for (int kp = 0; kp < 4; kp++) {
            split2(sacc[2*kp][0],   sacc[2*kp][1],   phi[kp][0], plo[kp][0]);
            split2(sacc[2*kp][2],   sacc[2*kp][3],   phi[kp][1], plo[kp][1]);
            split2(sacc[2*kp+1][0], sacc[2*kp+1][1], phi[kp][2], plo[kp][2]);
            split2(sacc[2*kp+1][2], sacc[2*kp+1][3], phi[kp][3], plo[kp][3]);
        }

#pragma unroll
        for (int kp = 0; kp < 4; kp++) {
            uint32_t rowoff = (uint32_t)(kp * 16 * KVS) * 2;
#pragma unroll
            for (int ng = 0; ng < 8; ng++) {
                uint32_t coff = rowoff + (uint32_t)(ng * 16) * 2;
                uint32_t vh4[4], vl4[4];
                LDMATRIX_X4_T(vh4[0], vh4[1], vh4[2], vh4[3], vh_base + coff);
                LDMATRIX_X4_T(vl4[0], vl4[1], vl4[2], vl4[3], vl_base + coff);
                MMA_BF16(oacc[2*ng],   phi[kp][0], phi[kp][1], phi[kp][2], phi[kp][3], vh4[0], vh4[1]);
                MMA_BF16(oacc[2*ng+1], phi[kp][0], phi[kp][1], phi[kp][2], phi[kp][3], vh4[2], vh4[3]);
                MMA_BF16(oacc[2*ng],   plo[kp][0], plo[kp][1], plo[kp][2], plo[kp][3], vh4[0], vh4[1]);
                MMA_BF16(oacc[2*ng+1], plo[kp][0], plo[kp][1], plo[kp][2], plo[kp][3], vh4[2], vh4[3]);
                MMA_BF16(oacc[2*ng],   phi[kp][0], phi[kp][1], phi[kp][2], phi[kp][3], vl4[0], vl4[1]);
                MMA_BF16(oacc[2*ng+1], phi[kp][0], phi[kp][1], phi[kp][2], phi[kp][3], vl4[2], vl4[3]);
            }
        }
        __syncthreads();
        s ^= 1;
    }

    float il0 = 1.0f / lsum[0];
    float il1 = 1.0f / lsum[1];
    const int row0 = qbase + trow;
#pragma unroll
    for (int nf = 0; nf < 16; nf++) {
        int col = head * HD + nf * 8 + tc2;
        uint32_t hh, ll;
        split2(oacc[nf][0] * il0, oacc[nf][1] * il0, hh, ll);
        *(uint32_t*)&Yh[(size_t)row0 * C_DIM + col] = hh;
        *(uint32_t*)&Yl[(size_t)row0 * C_DIM + col] = ll;
        split2(oacc[nf][2] * il1, oacc[nf][3] * il1, hh, ll);
        *(uint32_t*)&Yh[(size_t)(row0 + 8) * C_DIM + col] = hh;
        *(uint32_t*)&Yl[(size_t)(row0 + 8) * C_DIM + col] = ll;
    }
}

// ---------------------------------------------------------------------------
// Launch: 1 prep_all, 2 gemm_qkv, 3 rope_k, 4 attention (profiled), 5 Wo.
// ---------------------------------------------------------------------------
extern "C" void kernel_launch(void* const* d_in, const int* in_sizes, int n_in,
                              void* d_out, int out_size)
{
    const float* x  = (const float*)d_in[0];
    const float* Wq = (const float*)d_in[1];
    const float* Wk = (const float*)d_in[2];
    const float* Wv = (const float*)d_in[3];
    const float* Wo = (const float*)d_in[4];
    float* out = (float*)d_out;

    float *Q, *Kp;
    cudaGetSymbolAddress((void**)&Q,  g_Q);
    cudaGetSymbolAddress((void**)&Kp, g_K);

    __nv_bfloat16 *xh, *xl, *yh, *yl, *woh, *wol;
    cudaGetSymbolAddress((void**)&xh, g_xh);
    cudaGetSymbolAddress((void**)&xl, g_xl);
    cudaGetSymbolAddress((void**)&yh, g_yh);
    cudaGetSymbolAddress((void**)&yl, g_yl);
    cudaGetSymbolAddress((void**)&woh, g_wot_h);
    cudaGetSymbolAddress((void**)&wol, g_wot_l);

    static bool attr_done = false;
    if (!attr_done) {
        cudaFuncSetAttribute(gemm_one, cudaFuncAttributeMaxDynamicSharedMemorySize, G2_SMEM);
        cudaFuncSetAttribute(gemm_qkv, cudaFuncAttributeMaxDynamicSharedMemorySize, G2_SMEM);
        cudaFuncSetAttribute(attn_tc_kernel, cudaFuncAttributeMaxDynamicSharedMemorySize, ATT_SMEM);
        attr_done = true;
    }

    // 1: all prep (weight transposes, x split, rope table)
    prep_all<<<dim3(64, 64, 7), dim3(32, 8)>>>(x, Wq, Wk, Wv, Wo);
    // 2: Q + K + V projections (single packed launch, 384 blocks)
    gemm_qkv<<<dim3(24, T_LEN / 256), 256, G2_SMEM>>>(xh, xl, Q, Kp);
    // 3: K RoPE + split
    rope_k_kernel<<<(T_LEN * HKV * 32) / 256, 256>>>(Kp);
    // 4: attention (profiled slot)
    attn_tc_kernel<<<dim3(T_LEN / 32, HKV), 256, ATT_SMEM>>>(Q, yh, yl);
    // 5: output projection
    gemm_one<<<dim3(C_DIM / 128, T_LEN / 256), 256, G2_SMEM>>>(yh, yl, woh, wol, out, T_LEN, C_DIM, C_DIM);
}

// round 16
// speedup vs baseline: 1.0875x; 1.0045x over previous
#include <cuda_runtime.h>
#include <cuda_bf16.h>
#include <math.h>
#include <float.h>
#include <stdint.h>

// Problem constants
#define T_LEN   4096
#define C_DIM   2048
#define HQ      16
#define HKV     4
#define HD      128
#define WIN     1024
#define NKV     (HKV * HD)     // 512

#define SCQ_CONST 0.1275174541395871f  // 1/sqrt(128) * log2(e)

// fp32 scratch
__device__ float g_Q[T_LEN * HQ * HD];
__device__ float g_K[T_LEN * NKV];
__device__ float g_cos[T_LEN * 64];
__device__ float g_sin[T_LEN * 64];

// bf16 split operands
__device__ __nv_bfloat16 g_xh[T_LEN * C_DIM],  g_xl[T_LEN * C_DIM];
__device__ __nv_bfloat16 g_yh[T_LEN * C_DIM],  g_yl[T_LEN * C_DIM];
__device__ __nv_bfloat16 g_ksh[T_LEN * NKV],   g_ksl[T_LEN * NKV];
__device__ __nv_bfloat16 g_vsh[T_LEN * NKV],   g_vsl[T_LEN * NKV];
__device__ __nv_bfloat16 g_wqt_h[C_DIM * C_DIM], g_wqt_l[C_DIM * C_DIM];
__device__ __nv_bfloat16 g_wkt_h[NKV * C_DIM],   g_wkt_l[NKV * C_DIM];
__device__ __nv_bfloat16 g_wvt_h[NKV * C_DIM],   g_wvt_l[NKV * C_DIM];
__device__ __nv_bfloat16 g_wot_h[C_DIM * C_DIM], g_wot_l[C_DIM * C_DIM];

// ---------------------------------------------------------------------------
// helpers
// ---------------------------------------------------------------------------
__device__ __forceinline__ uint32_t smem_u32(const void* p) {
    return (uint32_t)__cvta_generic_to_shared(p);
}

__device__ __forceinline__ void split2(float a, float b, uint32_t& hi, uint32_t& lo) {
    __nv_bfloat16 ah = __float2bfloat16_rn(a);
    __nv_bfloat16 bh = __float2bfloat16_rn(b);
    __nv_bfloat162 h(ah, bh);
    hi = *(uint32_t*)&h;
    __nv_bfloat162 l(__float2bfloat16_rn(a - __bfloat162float(ah)),
                     __float2bfloat16_rn(b - __bfloat162float(bh)));
    lo = *(uint32_t*)&l;
}

#define LDMATRIX_X4(R0,R1,R2,R3,ADDR) \
    asm volatile("ldmatrix.sync.aligned.m8n8.x4.shared.b16 {%0,%1,%2,%3}, [%4];" \
        : "=r"(R0), "=r"(R1), "=r"(R2), "=r"(R3) : "r"(ADDR))

#define LDMATRIX_X4_T(R0,R1,R2,R3,ADDR) \
    asm volatile("ldmatrix.sync.aligned.m8n8.x4.trans.shared.b16 {%0,%1,%2,%3}, [%4];" \
        : "=r"(R0), "=r"(R1), "=r"(R2), "=r"(R3) : "r"(ADDR))

#define MMA_BF16(D, A0,A1,A2,A3, B0,B1) \
    asm volatile("mma.sync.aligned.m16n8k16.row.col.f32.bf16.bf16.f32 " \
        "{%0,%1,%2,%3}, {%4,%5,%6,%7}, {%8,%9}, {%0,%1,%2,%3};" \
        : "+f"((D)[0]), "+f"((D)[1]), "+f"((D)[2]), "+f"((D)[3]) \
        : "r"(A0), "r"(A1), "r"(A2), "r"(A3), "r"(B0), "r"(B1))

__device__ __forceinline__ void cp_async16(uint32_t dst, const void* src) {
    asm volatile("cp.async.cg.shared.global [%0], [%1], 16;" :: "r"(dst), "l"(src));
}
__device__ __forceinline__ void cp_commit() {
    asm volatile("cp.async.commit_group;" ::: "memory");
}
template <int NN> __device__ __forceinline__ void cp_wait() {
    asm volatile("cp.async.wait_group %0;" :: "n"(NN) : "memory");
}

// ---------------------------------------------------------------------------
// Merged prep: z=0 Wq-T, z=1 Wo-T, z=2 Wk-T, z=3 Wv-T, z=4,5 split x,
// z=6 rope table. Block (32,8).
// ---------------------------------------------------------------------------
__device__ __forceinline__ void transpose_split_body(
    const float* __restrict__ W, __nv_bfloat16* __restrict__ Th,
    __nv_bfloat16* __restrict__ Tl, int Kd, int Nd, int bx, int by)
{
    __shared__ float tile[32][33];
    const int x = threadIdx.x;
    const int y = threadIdx.y;
#pragma unroll
    for (int j = 0; j < 32; j += 8)
        tile[y + j][x] = W[(size_t)(by * 32 + y + j) * Nd + bx * 32 + x];
    __syncthreads();
#pragma unroll
    for (int j = 0; j < 32; j += 8) {
        float v = tile[x][y + j];
        __nv_bfloat16 h = __float2bfloat16_rn(v);
        size_t o = (size_t)(bx * 32 + y + j) * Kd + by * 32 + x;
        Th[o] = h;
        Tl[o] = __float2bfloat16_rn(v - __bfloat162float(h));
    }
}

__global__ void prep_all(const float* __restrict__ x,
                         const float* __restrict__ Wq, const float* __restrict__ Wk,
                         const float* __restrict__ Wv, const float* __restrict__ Wo)
{
    const int z = blockIdx.z, bx = blockIdx.x, by = blockIdx.y;
    const int tid = threadIdx.y * 32 + threadIdx.x;
    if (z == 0)       transpose_split_body(Wq, g_wqt_h, g_wqt_l, C_DIM, C_DIM, bx, by);
    else if (z == 1)  transpose_split_body(Wo, g_wot_h, g_wot_l, C_DIM, C_DIM, bx, by);
    else if (z == 2) { if (bx < 16) transpose_split_body(Wk, g_wkt_h, g_wkt_l, C_DIM, NKV, bx, by); }
    else if (z == 3) { if (bx < 16) transpose_split_body(Wv, g_wvt_h, g_wvt_l, C_DIM, NKV, bx, by); }
    else if (z <= 5) {
        int i = ((z - 4) * 4096 + by * 64 + bx) * 256 + tid;
        float4 v = ((const float4*)x)[i];
        uint32_t h0, l0, h1, l1;
        split2(v.x, v.y, h0, l0);
        split2(v.z, v.w, h1, l1);
        ((uint2*)g_xh)[i] = make_uint2(h0, h1);
        ((uint2*)g_xl)[i] = make_uint2(l0, l1);
    } else {
        if (by >= 16) return;
        __shared__ float s_invf[64];
        if (tid < 64) {
            double e = exp(-(double)tid * (log(10000.0) / 64.0));
            s_invf[tid] = (float)e;
        }
        __syncthreads();
        int idx = (by * 64 + bx) * 256 + tid;
        int t = idx >> 6;
        int j = idx & 63;
        float ang = (float)t * s_invf[j];
        float s, c;
        sincosf(ang, &s, &c);
        g_cos[idx] = c;
        g_sin[idx] = s;
    }
}

// ---------------------------------------------------------------------------
// bf16x3 GEMM: 256x128 block tile, BK=64, 256 threads, 2-stage pipeline,
// one barrier per iteration.
// ---------------------------------------------------------------------------
#define G2_AH 0
#define G2_AL 32768
#define G2_BH 65536
#define G2_BL 81920
#define G2_STAGE 98304
#define G2_SMEM  (2 * G2_STAGE)

__device__ __forceinline__ void g_load_stage(uint32_t dstbase,
    const __nv_bfloat16* __restrict__ Ah, const __nv_bfloat16* __restrict__ Al,
    const __nv_bfloat16* __restrict__ Bh, const __nv_bfloat16* __restrict__ Bl,
    int bm, int bn, int k0, int K, int tid)
{
    const int row = tid >> 3;
    const int c   = tid & 7;
    const uint32_t swc = (uint32_t)((c ^ (row & 7)) << 4);
#pragma unroll
    for (int jj = 0; jj < 8; jj++) {
        int r = row + 32 * jj;
        uint32_t so = (uint32_t)r * 128 + swc;
        size_t ga = (size_t)(bm + r) * K + k0 + c * 8;
        cp_async16(dstbase + G2_AH + so, Ah + ga);
        cp_async16(dstbase + G2_AL + so, Al + ga);
    }
#pragma unroll
    for (int jj = 0; jj < 4; jj++) {
        int r = row + 32 * jj;
        uint32_t so = (uint32_t)r * 128 + swc;
        size_t gb = (size_t)(bn + r) * K + k0 + c * 8;
        cp_async16(dstbase + G2_BH + so, Bh + gb);
        cp_async16(dstbase + G2_BL + so, Bl + gb);
    }
}

__device__ void gemm_body(
    const __nv_bfloat16* __restrict__ Ah, const __nv_bfloat16* __restrict__ Al,
    const __nv_bfloat16* __restrict__ Bh, const __nv_bfloat16* __restrict__ Bl,
    float* __restrict__ C, __nv_bfloat16* __restrict__ Ch, __nv_bfloat16* __restrict__ Cl,
    int splitout, int M, int N, int K, int bxx, int byy)
{
    extern __shared__ char smg[];
    const int tid  = threadIdx.x;
    const int wid  = tid >> 5;
    const int lane = tid & 31;
    const int warp_m = wid & 3;
    const int warp_n = wid >> 2;
    const int bm = byy * 256;
    const int bn = bxx * 128;
    const uint32_t sbase = smem_u32(smg);

    const int ar  = (lane & 7) | (((lane >> 3) & 1) << 3);
    const int ag  = lane >> 4;
    const int ar7 = ar & 7;
    const int br  = (lane & 7) | ((lane >> 4) << 3);
    const int bg  = (lane >> 3) & 1;
    const int br7 = lane & 7;

    uint32_t a_ro[4], b_ro[4];
#pragma unroll
    for (int mi = 0; mi < 4; mi++)
        a_ro[mi] = (uint32_t)(warp_m * 64 + mi * 16 + ar) * 128 + G2_AH;
#pragma unroll
    for (int ng = 0; ng < 4; ng++)
        b_ro[ng] = (uint32_t)(warp_n * 64 + ng * 16 + br) * 128 + G2_BH;

    float acc[4][8][4];
#pragma unroll
    for (int mi = 0; mi < 4; mi++)
#pragma unroll
        for (int nf = 0; nf < 8; nf++)
#pragma unroll
            for (int e = 0; e < 4; e++) acc[mi][nf][e] = 0.0f;

    const int NK = K >> 6;

    g_load_stage(sbase, Ah, Al, Bh, Bl, bm, bn, 0, K, tid);
    cp_commit();

    for (int i = 0; i < NK; i++) {
        cp_wait<0>();
        __syncthreads();

        if (i + 1 < NK) {
            g_load_stage(sbase + ((i + 1) & 1) * G2_STAGE, Ah, Al, Bh, Bl,
                         bm, bn, (i + 1) * 64, K, tid);
            cp_commit();
        }

        const uint32_t stb = sbase + (i & 1) * G2_STAGE;
#pragma unroll
        for (int ks = 0; ks < 4; ks++) {
            const uint32_t cA = (uint32_t)(((ks * 2 + ag) ^ ar7) << 4);
            const uint32_t cB = (uint32_t)(((ks * 2 + bg) ^ br7) << 4);
            uint32_t ahi[4][4], alo[4][4];
#pragma unroll
            for (int mi = 0; mi < 4; mi++) {
                uint32_t ad = stb + a_ro[mi] + cA;
                LDMATRIX_X4(ahi[mi][0], ahi[mi][1], ahi[mi][2], ahi[mi][3], ad);
                LDMATRIX_X4(alo[mi][0], alo[mi][1], alo[mi][2], alo[mi][3], ad + 32768);
            }
            uint32_t bhi[4][4], blo[4][4];
#pragma unroll
            for (int ng = 0; ng < 4; ng++) {
                uint32_t bd = stb + b_ro[ng] + cB;
                LDMATRIX_X4(bhi[ng][0], bhi[ng][1], bhi[ng][2], bhi[ng][3], bd);
                LDMATRIX_X4(blo[ng][0], blo[ng][1], blo[ng][2], blo[ng][3], bd + 16384);
            }
#pragma unroll
            for (int mi = 0; mi < 4; mi++)
#pragma unroll
                for (int ng = 0; ng < 4; ng++) {
                    MMA_BF16(acc[mi][2*ng],   ahi[mi][0], ahi[mi][1], ahi[mi][2], ahi[mi][3], bhi[ng][0], bhi[ng][1]);
                    MMA_BF16(acc[mi][2*ng+1], ahi[mi][0], ahi[mi][1], ahi[mi][2], ahi[mi][3], bhi[ng][2], bhi[ng][3]);
                }
#pragma unroll
            for (int mi = 0; mi < 4; mi++)
#pragma unroll
                for (int ng = 0; ng < 4; ng++) {
                    MMA_BF16(acc[mi][2*ng],   ahi[mi][0], ahi[mi][1], ahi[mi][2], ahi[mi][3], blo[ng][0], blo[ng][1]);
                    MMA_BF16(acc[mi][2*ng+1], ahi[mi][0], ahi[mi][1], ahi[mi][2], ahi[mi][3], blo[ng][2], blo[ng][3]);
                }
#pragma unroll
            for (int mi = 0; mi < 4; mi++)
#pragma unroll
                for (int ng = 0; ng < 4; ng++) {
                    MMA_BF16(acc[mi][2*ng],   alo[mi][0], alo[mi][1], alo[mi][2], alo[mi][3], bhi[ng][0], bhi[ng][1]);
                    MMA_BF16(acc[mi][2*ng+1], alo[mi][0], alo[mi][1], alo[mi][2], alo[mi][3], bhi[ng][2], bhi[ng][3]);
                }
        }
    }

    const int trow = lane >> 2;
    const int tcol = (lane & 3) << 1;
#pragma unroll
    for (int mi = 0; mi < 4; mi++) {
#pragma unroll
        for (int nf = 0; nf < 8; nf++) {
            int rg = bm + warp_m * 64 + mi * 16 + trow;
            int cg = bn + warp_n * 64 + nf * 8 + tcol;
            if (!splitout) {
                *(float2*)&C[(size_t)rg * N + cg]       = make_float2(acc[mi][nf][0], acc[mi][nf][1]);
                *(float2*)&C[(size_t)(rg + 8) * N + cg] = make_float2(acc[mi][nf][2], acc[mi][nf][3]);
            } else {
                uint32_t hh, ll;
                split2(acc[mi][nf][0], acc[mi][nf][1], hh, ll);
                *(uint32_t*)&Ch[(size_t)rg * N + cg] = hh;
                *(uint32_t*)&Cl[(size_t)rg * N + cg] = ll;
                split2(acc[mi][nf][2], acc[mi][nf][3], hh, ll);
                *(uint32_t*)&Ch[(size_t)(rg + 8) * N + cg] = hh;
                *(uint32_t*)&Cl[(size_t)(rg + 8) * N + cg] = ll;
            }
        }
    }
}

// Packed QKV: grid (24, 16). bx<16 -> Q, 16..19 -> K, 20..23 -> V (split out).
__global__ __launch_bounds__(256)
void gemm_qkv(const __nv_bfloat16* __restrict__ xh, const __nv_bfloat16* __restrict__ xl,
              float* __restrict__ Qout, float* __restrict__ Kout)
{
    const int bx = blockIdx.x;
    if (bx < 16)
        gemm_body(xh, xl, g_wqt_h, g_wqt_l, Qout, nullptr, nullptr, 0,
                  T_LEN, HQ * HD, C_DIM, bx, blockIdx.y);
    else if (bx < 20)
        gemm_body(xh, xl, g_wkt_h, g_wkt_l, Kout, nullptr, nullptr, 0,
                  T_LEN, NKV, C_DIM, bx - 16, blockIdx.y);
    else
        gemm_body(xh, xl, g_wvt_h, g_wvt_l, nullptr, g_vsh, g_vsl, 1,
                  T_LEN, NKV, C_DIM, bx - 20, blockIdx.y);
}

__global__ __launch_bounds__(256)
void gemm_one(const __nv_bfloat16* Ah, const __nv_bfloat16* Al,
              const __nv_bfloat16* Bh, const __nv_bfloat16* Bl,
              float* C, int M, int N, int K)
{
    gemm_body(Ah, Al, Bh, Bl, C, nullptr, nullptr, 0, M, N, K, blockIdx.x, blockIdx.y);
}

// ---------------------------------------------------------------------------
// K-only RoPE apply + split.
// ---------------------------------------------------------------------------
__global__ void rope_k_kernel(const float* __restrict__ K)
{
    int idx = blockIdx.x * blockDim.x + threadIdx.x;
    int t = idx >> 7;
    int rem = idx & 127;
    int h = rem >> 5;
    int j2 = (rem & 31) << 1;
    size_t o = (size_t)t * NKV + h * HD;
    const float* p = K + o;
    float2 x0 = *(const float2*)(p + j2);
    float2 x1 = *(const float2*)(p + j2 + 64);
    float2 cv = *(const float2*)(g_cos + t * 64 + j2);
    float2 sv = *(const float2*)(g_sin + t * 64 + j2);
    float r0a = x0.x * cv.x - x1.x * sv.x;
    float r0b = x0.y * cv.y - x1.y * sv.y;
    float r1a = x1.x * cv.x + x0.x * sv.x;
    float r1b = x1.y * cv.y + x0.y * sv.y;
    uint32_t hh, ll;
    split2(r0a, r0b, hh, ll);
    *(uint32_t*)&g_ksh[o + j2] = hh;
    *(uint32_t*)&g_ksl[o + j2] = ll;
    split2(r1a, r1b, hh, ll);
    *(uint32_t*)&g_ksh[o + j2 + 64] = hh;
    *(uint32_t*)&g_ksl[o + j2 + 64] = ll;
}

// ---------------------------------------------------------------------------
// Flash attention, GQA-packed (32 q x 4 heads / block, 64-key tiles, 256 thr),
// Q RoPE+scale+split fused, heavy blocks first, ONE barrier per KV tile
// (GEMM-style pipeline: loads issued only after the post-wait barrier).
// ---------------------------------------------------------------------------
#define KVS   136
#define AR_SZ (64 * KVS * 2)
#define A_KH  0
#define A_KL  AR_SZ
#define A_VH  (2 * AR_SZ)
#define A_VL  (3 * AR_SZ)
#define ATT_STAGE (4 * AR_SZ)
#define ATT_SMEM  (2 * ATT_STAGE)

__device__ __forceinline__ void attn_load_kv(uint32_t dstbase, int jb, int kvh, int tid)
{
#pragma unroll
    for (int i = 0; i < 4; i++) {
        int idx = tid + 256 * i;
        int row = idx >> 4;
        int c16 = idx & 15;
        uint32_t so = (uint32_t)row * (KVS * 2) + c16 * 16;
        size_t g = (size_t)(jb + row) * NKV + kvh * HD + c16 * 8;
        cp_async16(dstbase + A_KH + so, g_ksh + g);
        cp_async16(dstbase + A_KL + so, g_ksl + g);
        cp_async16(dstbase + A_VH + so, g_vsh + g);
        cp_async16(dstbase + A_VL + so, g_vsl + g);
    }
}

__global__ __launch_bounds__(256)
void attn_tc_kernel(const float* __restrict__ Qf,
                    __nv_bfloat16* __restrict__ Yh, __nv_bfloat16* __restrict__ Yl)
{
    extern __shared__ char sma[];
    const uint32_t sbase = smem_u32(sma);

    const int qb  = gridDim.x - 1 - blockIdx.x;
    const int kvh = blockIdx.y;
    const int tid  = threadIdx.x;
    const int wid  = tid >> 5;
    const int lane = tid & 31;
    const int trow = lane >> 2;
    const int tc2  = (lane & 3) << 1;

    const int q0    = qb * 32;
    const int head  = kvh * 4 + (wid >> 1);
    const int qbase = q0 + ((wid & 1) << 4);

    // Q fragments: fp32 load, RoPE rotate + scale + split in registers.
    uint32_t qhi[8][4], qlo[8][4];
#pragma unroll
    for (int ks = 0; ks < 4; ks++) {
#pragma unroll
        for (int r = 0; r < 4; r++) {
            int row = qbase + trow + ((r & 1) << 3);
            int j = ks * 16 + ((r >> 1) << 3) + tc2;
            const float* qp = Qf + (size_t)row * C_DIM + head * HD;
            float2 x0 = *(const float2*)(qp + j);
            float2 x1 = *(const float2*)(qp + j + 64);
            float2 cv = *(const float2*)(g_cos + row * 64 + j);
            float2 sv = *(const float2*)(g_sin + row * 64 + j);
            float r0a = (x0.x * cv.x - x1.x * sv.x) * SCQ_CONST;
            float r0b = (x0.y * cv.y - x1.y * sv.y) * SCQ_CONST;
            float r1a = (x1.x * cv.x + x0.x * sv.x) * SCQ_CONST;
            float r1b = (x1.y * cv.y + x0.y * sv.y) * SCQ_CONST;
            split2(r0a, r0b, qhi[ks][r],     qlo[ks][r]);
            split2(r1a, r1b, qhi[ks + 4][r], qlo[ks + 4][r]);
        }
    }

    float oacc[16][4];
#pragma unroll
    for (int nf = 0; nf < 16; nf++)
#pragma unroll
        for (int e = 0; e < 4; e++) oacc[nf][e] = 0.0f;
    float m2[2]   = { -1e30f, -1e30f };
    float lsum[2] = { 0.0f, 0.0f };

    int jmin = q0 - (WIN - 1);
    if (jmin < 0) jmin = 0;
    const int kb0 = jmin >> 6;
    const int kb1 = (q0 + 31) >> 6;

    const int krow    = (lane & 7) + ((lane >> 4) << 3);
    const int kcoloff = ((lane >> 3) & 1) << 3;
    const int vrow    = (lane & 7) + (((lane >> 3) & 1) << 3);
    const int vcoloff = (lane >> 4) << 3;

    const uint32_t kh_ro = (uint32_t)(krow * KVS + kcoloff) * 2;
    const uint32_t vh_ro = (uint32_t)(vrow * KVS + vcoloff) * 2;
    const uint32_t KROW16 = (uint32_t)(16 * KVS) * 2;

    // Prologue: load first tile into stage 0
    attn_load_kv(sbase, kb0 * 64, kvh, tid);
    cp_commit();

    int s = 0;
    for (int kb = kb0; kb <= kb1; kb++) {
        const int jb = kb * 64;
        cp_wait<0>();          // this thread's load(kb) complete
        __syncthreads();       // data visible; all warps done compute(kb-1)

        if (kb < kb1) {        // issue next-tile load AFTER the barrier
            attn_load_kv(sbase + (s ^ 1) * ATT_STAGE, (kb + 1) * 64, kvh, tid);
            cp_commit();
        }

        const uint32_t stb = sbase + s * ATT_STAGE;
        const uint32_t kh_base = stb + A_KH + kh_ro;
        const uint32_t vh_base = stb + A_VH + vh_ro;
        const uint32_t vl_base = stb + A_VL + vh_ro;

        float sacc[8][4];
#pragma unroll
        for (int f = 0; f < 8; f++)
#pragma unroll
            for (int e = 0; e < 4; e++) sacc[f][e] = 0.0f;

#pragma unroll
        for (int ks = 0; ks < 8; ks++) {
            uint32_t off = (uint32_t)(ks * 16) * 2;
#pragma unroll
            for (int g = 0; g < 4; g++) {
                uint32_t bh[4], bl[4];
                uint32_t ad = kh_base + off + g * KROW16;
                LDMATRIX_X4(bh[0], bh[1], bh[2], bh[3], ad);
                LDMATRIX_X4(bl[0], bl[1], bl[2], bl[3], ad + AR_SZ);
                const int f0 = 2 * g, f1 = 2 * g + 1;
                MMA_BF16(sacc[f0], qhi[ks][0], qhi[ks][1], qhi[ks][2], qhi[ks][3], bh[0], bh[1]);
                MMA_BF16(sacc[f1], qhi[ks][0], qhi[ks][1], qhi[ks][2], qhi[ks][3], bh[2], bh[3]);
                MMA_BF16(sacc[f0], qlo[ks][0], qlo[ks][1], qlo[ks][2], qlo[ks][3], bh[0], bh[1]);
                MMA_BF16(sacc[f1], qlo[ks][0], qlo[ks][1], qlo[ks][2], qlo[ks][3], bh[2], bh[3]);
                MMA_BF16(sacc[f0], qhi[ks][0], qhi[ks][1], qhi[ks][2], qhi[ks][3], bl[0], bl[1]);
                MMA_BF16(sacc[f1], qhi[ks][0], qhi[ks][1], qhi[ks][2], qhi[ks][3], bl[2], bl[3]);
            }
        }

        const bool full = (jb + 64 <= q0) && (jb >= q0 - (WIN - 32));
        if (!full) {
#pragma unroll
            for (int f = 0; f < 8; f++) {
                int j0 = jb + f * 8 + tc2;
#pragma unroll
                for (int e = 0; e < 4; e++) {
                    int j  = j0 + (e & 1);
                    int qi = qbase + trow + ((e >> 1) << 3);
                    bool ok = (j <= qi) && ((qi - j) < WIN);
                    if (!ok) sacc[f][e] = -1e30f;
                }
            }
        }

        float bm0 = -1e30f, bm1 = -1e30f;
#pragma unroll
        for (int f = 0; f < 8; f++) {
            bm0 = fmaxf(bm0, fmaxf(sacc[f][0], sacc[f][1]));
            bm1 = fmaxf(bm1, fmaxf(sacc[f][2], sacc[f][3]));
        }
        bm0 = fmaxf(bm0, __shfl_xor_sync(0xffffffffu, bm0, 1));
        bm0 = fmaxf(bm0, __shfl_xor_sync(0xffffffffu, bm0, 2));
        bm1 = fmaxf(bm1, __shfl_xor_sync(0xffffffffu, bm1, 1));
        bm1 = fmaxf(bm1, __shfl_xor_sync(0xffffffffu, bm1, 2));

        float mn0 = fmaxf(m2[0], bm0);
        float mn1 = fmaxf(m2[1], bm1);
        float mm0 = fmaxf(mn0, -1e20f);
        float mm1 = fmaxf(mn1, -1e20f);
        float f0 = exp2f(m2[0] - mm0);
        float f1 = exp2f(m2[1] - mm1);
        m2[0] = mn0; m2[1] = mn1;

        float ps0 = 0.0f, ps1 = 0.0f;
#pragma unroll
        for (int f = 0; f < 8; f++) {
            sacc[f][0] = exp2f(sacc[f][0] - mm0);
            sacc[f][1] = exp2f(sacc[f][1] - mm0);
            sacc[f][2] = exp2f(sacc[f][2] - mm1);
            sacc[f][3] = exp2f(sacc[f][3] - mm1);
            ps0 += sacc[f][0] + sacc[f][1];
            ps1 += sacc[f][2] + sacc[f][3];
        }
        ps0 += __shfl_xor_sync(0xffffffffu, ps0, 1);
        ps0 += __shfl_xor_sync(0xffffffffu, ps0, 2);
        ps1 += __shfl_xor_sync(0xffffffffu, ps1, 1);
        ps1 += __shfl_xor_sync(0xffffffffu, ps1, 2);
        lsum[0] = lsum[0] * f0 + ps0;
        lsum[1] = lsum[1] * f1 + ps1;

#pragma unroll
        for (int nf = 0; nf < 16; nf++) {
            oacc[nf][0] *= f0; oacc[nf][1] *= f0;
            oacc[nf][2] *= f1; oacc[nf][3] *= f1;
        }

        uint32_t phi[4][4], plo[4][4];
#pragma unroll
        for (int kp = 0; kp < 4; kp++) {
            split2(sacc[2*kp][0],   sacc[2*kp][1],   phi[kp][0], plo[kp][0]);
            split2(sacc[2*kp][2],   sacc[2*kp][3],   phi[kp][1], plo[kp][1]);
            split2(sacc[2*kp+1][0], sacc[2*kp+1][1], phi[kp][2], plo[kp][2]);
            split2(sacc[2*kp+1][2], sacc[2*kp+1][3], phi[kp][3], plo[kp][3]);
        }

#pragma unroll
        for (int kp = 0; kp < 4; kp++) {
            uint32_t rowoff = (uint32_t)(kp * 16 * KVS) * 2;
#pragma unroll
            for (int ng = 0; ng < 8; ng++) {
                uint32_t coff = rowoff + (uint32_t)(ng * 16) * 2;
                uint32_t vh4[4], vl4[4];
                LDMATRIX_X4_T(vh4[0], vh4[1], vh4[2], vh4[3], vh_base + coff);
                LDMATRIX_X4_T(vl4[0], vl4[1], vl4[2], vl4[3], vl_base + coff);
                MMA_BF16(oacc[2*ng],   phi[kp][0], phi[kp][1], phi[kp][2], phi[kp][3], vh4[0], vh4[1]);
                MMA_BF16(oacc[2*ng+1], phi[kp][0], phi[kp][1], phi[kp][2], phi[kp][3], vh4[2], vh4[3]);
                MMA_BF16(oacc[2*ng],   plo[kp][0], plo[kp][1], plo[kp][2], plo[kp][3], vh4[0], vh4[1]);
                MMA_BF16(oacc[2*ng+1], plo[kp][0], plo[kp][1], plo[kp][2], plo[kp][3], vh4[2], vh4[3]);
                MMA_BF16(oacc[2*ng],   phi[kp][0], phi[kp][1], phi[kp][2], phi[kp][3], vl4[0], vl4[1]);
                MMA_BF16(oacc[2*ng+1], phi[kp][0], phi[kp][1], phi[kp][2], phi[kp][3], vl4[2], vl4[3]);
            }
        }
        // no end barrier: next iteration's post-wait barrier protects stage reuse
        s ^= 1;
    }

    float il0 = 1.0f / lsum[0];
    float il1 = 1.0f / lsum[1];
    const int row0 = qbase + trow;
#pragma unroll
    for (int nf = 0; nf < 16; nf++) {
        int col = head * HD + nf * 8 + tc2;
        uint32_t hh, ll;
        split2(oacc[nf][0] * il0, oacc[nf][1] * il0, hh, ll);
        *(uint32_t*)&Yh[(size_t)row0 * C_DIM + col] = hh;
        *(uint32_t*)&Yl[(size_t)row0 * C_DIM + col] = ll;
        split2(oacc[nf][2] * il1, oacc[nf][3] * il1, hh, ll);
        *(uint32_t*)&Yh[(size_t)(row0 + 8) * C_DIM + col] = hh;
        *(uint32_t*)&Yl[(size_t)(row0 + 8) * C_DIM + col] = ll;
    }
}

// ---------------------------------------------------------------------------
// Launch: 1 prep_all, 2 gemm_qkv, 3 rope_k, 4 attention (profiled), 5 Wo.
// ---------------------------------------------------------------------------
extern "C" void kernel_launch(void* const* d_in, const int* in_sizes, int n_in,
                              void* d_out, int out_size)
{
    const float* x  = (const float*)d_in[0];
    const float* Wq = (const float*)d_in[1];
    const float* Wk = (const float*)d_in[2];
    const float* Wv = (const float*)d_in[3];
    const float* Wo = (const float*)d_in[4];
    float* out = (float*)d_out;

    float *Q, *Kp;
    cudaGetSymbolAddress((void**)&Q,  g_Q);
    cudaGetSymbolAddress((void**)&Kp, g_K);

    __nv_bfloat16 *xh, *xl, *yh, *yl, *woh, *wol;
    cudaGetSymbolAddress((void**)&xh, g_xh);
    cudaGetSymbolAddress((void**)&xl, g_xl);
    cudaGetSymbolAddress((void**)&yh, g_yh);
    cudaGetSymbolAddress((void**)&yl, g_yl);
    cudaGetSymbolAddress((void**)&woh, g_wot_h);
    cudaGetSymbolAddress((void**)&wol, g_wot_l);

    static bool attr_done = false;
    if (!attr_done) {
        cudaFuncSetAttribute(gemm_one, cudaFuncAttributeMaxDynamicSharedMemorySize, G2_SMEM);
        cudaFuncSetAttribute(gemm_qkv, cudaFuncAttributeMaxDynamicSharedMemorySize, G2_SMEM);
        cudaFuncSetAttribute(attn_tc_kernel, cudaFuncAttributeMaxDynamicSharedMemorySize, ATT_SMEM);
        attr_done = true;
    }

    // 1: all prep (weight transposes, x split, rope table)
    prep_all<<<dim3(64, 64, 7), dim3(32, 8)>>>(x, Wq, Wk, Wv, Wo);
    // 2: Q + K + V projections (single packed launch)
    gemm_qkv<<<dim3(24, T_LEN / 256), 256, G2_SMEM>>>(xh, xl, Q, Kp);
    // 3: K RoPE + split
    rope_k_kernel<<<(T_LEN * HKV * 32) / 256, 256>>>(Kp);
    // 4: attention (profiled slot)
    attn_tc_kernel<<<dim3(T_LEN / 32, HKV), 256, ATT_SMEM>>>(Q, yh, yl);
    // 5: output projection
    gemm_one<<<dim3(C_DIM / 128, T_LEN / 256), 256, G2_SMEM>>>(yh, yl, woh, wol, out, T_LEN, C_DIM, C_DIM);
}